// round 1
// baseline (speedup 1.0000x reference)
#include <cuda_runtime.h>
#include <cstdint>

// TCNN_INR: fused hash-grid encoding + MLP (48->128->128->1, bias-free, ReLU)
// Layout per CTA: 64 pixels, 256 threads, everything staged through smem.
// GEMMs use packed fp32x2 FMA (fma.rn.f32x2) with both operands loaded
// pre-packed from shared memory (pixel-paired A + pre-swapped copy, column-
// paired B) so the inner loop is pure LDS.128 + FFMA2.

#define PIX       64
#define THREADS   256
#define T_MASK    ((1u << 20) - 1u)

// scale_l = 16*1.5^l - 1 (exactly representable), res_l = ceil(scale)+1
__constant__ float c_scale[12] = {
    15.0f, 23.0f, 35.0f, 53.0f, 80.0f, 120.5f, 181.25f, 272.375f,
    409.0625f, 614.09375f, 921.640625f, 1382.9609375f};
__constant__ unsigned c_res[12] = {
    16u, 24u, 36u, 54u, 81u, 122u, 183u, 274u, 411u, 616u, 923u, 1384u};

// smem float offsets
#define OFF_W1   0        // 48*128  = 6144
#define OFF_W2   6144     // 128*128 = 16384
#define OFF_W3   22528    // 128
#define OFF_ENC  22656    // 48*64   = 3072   (feature-major: [k][pixel])
#define OFF_ENCS 25728    // 3072    (pixel pairs swapped)
#define OFF_H1   28800    // 128*64  = 8192
#define OFF_H1S  36992    // 8192
#define SMEM_FLOATS 45184
#define SMEM_BYTES  (SMEM_FLOATS * 4)   // 180736

__device__ __forceinline__ void cp16(unsigned dst, const void* src) {
    asm volatile("cp.async.cg.shared.global [%0], [%1], 16;\n" :: "r"(dst), "l"(src));
}
__device__ __forceinline__ void fma2(unsigned long long& d,
                                     unsigned long long a,
                                     unsigned long long b) {
    asm("fma.rn.f32x2 %0, %1, %2, %0;" : "+l"(d) : "l"(a), "l"(b));
}
__device__ __forceinline__ float lo32(unsigned long long v) {
    return __uint_as_float((unsigned)v);
}
__device__ __forceinline__ float hi32(unsigned long long v) {
    return __uint_as_float((unsigned)(v >> 32));
}

extern "C" __global__ void __launch_bounds__(THREADS, 1)
inr_fused_kernel(const float* __restrict__ tab,
                 const float* __restrict__ w1,
                 const float* __restrict__ w2,
                 const float* __restrict__ w3,
                 float* __restrict__ out)
{
    extern __shared__ float sm[];
    float* W1s  = sm + OFF_W1;
    float* W2s  = sm + OFF_W2;
    float* W3s  = sm + OFF_W3;
    float* ENC  = sm + OFF_ENC;
    float* ENCS = sm + OFF_ENCS;
    float* H1   = sm + OFF_H1;
    float* H1S  = sm + OFF_H1S;

    const int t = threadIdx.x;

    // ---- stage weights to smem via cp.async (overlapped with encoding) ----
    {
        unsigned s1 = (unsigned)__cvta_generic_to_shared(W1s);
        for (int i = t; i < 1536; i += THREADS) cp16(s1 + i * 16, w1 + i * 4);
        unsigned s2 = (unsigned)__cvta_generic_to_shared(W2s);
        for (int i = t; i < 4096; i += THREADS) cp16(s2 + i * 16, w2 + i * 4);
        if (t < 32) {
            unsigned s3 = (unsigned)__cvta_generic_to_shared(W3s);
            cp16(s3 + t * 16, w3 + t * 4);
        }
        asm volatile("cp.async.commit_group;\n" ::: "memory");
    }

    // ---- encoding: 64 pixels x 12 levels = 768 tasks, 3 per thread ----
    const int p   = t & 63;
    const int pid = blockIdx.x * PIX + p;
    const float cx = (float)(pid & 1023) * (1.0f / 1023.0f);
    const float cy = (float)(pid >> 10)  * (1.0f / 1023.0f);

    #pragma unroll
    for (int it = 0; it < 3; it++) {
        const int l = it * 4 + (t >> 6);       // warp-uniform level
        const float    sc  = c_scale[l];
        const unsigned res = c_res[l];

        float posx = fmaf(cx, sc, 0.5f);
        float fx = floorf(posx); float wx = posx - fx;
        float posy = fmaf(cy, sc, 0.5f);
        float fy = floorf(posy); float wy = posy - fy;
        unsigned px0 = (unsigned)fx, py0 = (unsigned)fy;
        unsigned px1 = min(px0 + 1u, res - 1u);
        unsigned py1 = min(py0 + 1u, res - 1u);

        unsigned i00, i10, i01, i11;
        if (l < 11) {   // dense levels (res^2 <= 2^20)
            i00 = px0 + py0 * res; i10 = px1 + py0 * res;
            i01 = px0 + py1 * res; i11 = px1 + py1 * res;
        } else {        // hashed level
            unsigned hy0 = py0 * 2654435761u, hy1 = py1 * 2654435761u;
            i00 = (px0 ^ hy0) & T_MASK; i10 = (px1 ^ hy0) & T_MASK;
            i01 = (px0 ^ hy1) & T_MASK; i11 = (px1 ^ hy1) & T_MASK;
        }

        const float4* tb = (const float4*)tab + ((size_t)l << 20);
        float4 v00 = __ldg(tb + i00);
        float4 v10 = __ldg(tb + i10);
        float4 v01 = __ldg(tb + i01);
        float4 v11 = __ldg(tb + i11);

        float w00 = (1.0f - wx) * (1.0f - wy);
        float w10 = wx * (1.0f - wy);
        float w01 = (1.0f - wx) * wy;
        float w11 = wx * wy;

        float fxv = v00.x * w00 + v10.x * w10 + v01.x * w01 + v11.x * w11;
        float fyv = v00.y * w00 + v10.y * w10 + v01.y * w01 + v11.y * w11;
        float fzv = v00.z * w00 + v10.z * w10 + v01.z * w01 + v11.z * w11;
        float fwv = v00.w * w00 + v10.w * w10 + v01.w * w01 + v11.w * w11;

        const int r = 4 * l;
        ENC [(r + 0) * 64 + p] = fxv;
        ENC [(r + 1) * 64 + p] = fyv;
        ENC [(r + 2) * 64 + p] = fzv;
        ENC [(r + 3) * 64 + p] = fwv;
        const int ps = p ^ 1;  // swapped-within-pixel-pair copy
        ENCS[(r + 0) * 64 + ps] = fxv;
        ENCS[(r + 1) * 64 + ps] = fyv;
        ENCS[(r + 2) * 64 + ps] = fzv;
        ENCS[(r + 3) * 64 + ps] = fwv;
    }

    asm volatile("cp.async.wait_group 0;\n" ::: "memory");
    __syncthreads();

    // ---- GEMM tiling: thread (pr, oc) -> pixels 4*pr.., cols 8*oc.. ----
    const int pr = t >> 4;
    const int oc = t & 15;
    const int pp = pr * 4;
    const int cc = oc * 8;

    unsigned long long ad[2][4], ax[2][4];

    // ================= GEMM1: h1 = relu(enc @ w1), K = 48 =================
    #pragma unroll
    for (int i = 0; i < 2; i++)
        #pragma unroll
        for (int j = 0; j < 4; j++) { ad[i][j] = 0ull; ax[i][j] = 0ull; }

    #pragma unroll 8
    for (int k = 0; k < 48; k++) {
        ulonglong2 A  = *(const ulonglong2*)(ENC  + k * 64 + pp);
        ulonglong2 S  = *(const ulonglong2*)(ENCS + k * 64 + pp);
        ulonglong2 B0 = *(const ulonglong2*)(W1s + k * 128 + cc);
        ulonglong2 B1 = *(const ulonglong2*)(W1s + k * 128 + cc + 4);
        unsigned long long b0 = B0.x, b1 = B0.y, b2 = B1.x, b3 = B1.y;
        fma2(ad[0][0], A.x, b0); fma2(ax[0][0], S.x, b0);
        fma2(ad[1][0], A.y, b0); fma2(ax[1][0], S.y, b0);
        fma2(ad[0][1], A.x, b1); fma2(ax[0][1], S.x, b1);
        fma2(ad[1][1], A.y, b1); fma2(ax[1][1], S.y, b1);
        fma2(ad[0][2], A.x, b2); fma2(ax[0][2], S.x, b2);
        fma2(ad[1][2], A.y, b2); fma2(ax[1][2], S.y, b2);
        fma2(ad[0][3], A.x, b3); fma2(ax[0][3], S.x, b3);
        fma2(ad[1][3], A.y, b3); fma2(ax[1][3], S.y, b3);
    }

    // relu + store h1 transposed [col][pixel] plus pair-swapped copy
    #pragma unroll
    for (int j = 0; j < 4; j++) {
        float q0 = fmaxf(lo32(ad[0][j]), 0.0f);  // pix0, col 2j
        float q1 = fmaxf(lo32(ax[0][j]), 0.0f);  // pix1, col 2j
        float q2 = fmaxf(lo32(ad[1][j]), 0.0f);  // pix2, col 2j
        float q3 = fmaxf(lo32(ax[1][j]), 0.0f);  // pix3, col 2j
        float r0 = fmaxf(hi32(ax[0][j]), 0.0f);  // pix0, col 2j+1
        float r1 = fmaxf(hi32(ad[0][j]), 0.0f);  // pix1, col 2j+1
        float r2 = fmaxf(hi32(ax[1][j]), 0.0f);  // pix2, col 2j+1
        float r3 = fmaxf(hi32(ad[1][j]), 0.0f);  // pix3, col 2j+1
        const int c0 = cc + 2 * j;
        *(float4*)(H1  + (c0    ) * 64 + pp) = make_float4(q0, q1, q2, q3);
        *(float4*)(H1  + (c0 + 1) * 64 + pp) = make_float4(r0, r1, r2, r3);
        *(float4*)(H1S + (c0    ) * 64 + pp) = make_float4(q1, q0, q3, q2);
        *(float4*)(H1S + (c0 + 1) * 64 + pp) = make_float4(r1, r0, r3, r2);
    }
    __syncthreads();

    // ================= GEMM2: h2 = relu(h1 @ w2), K = 128 ==================
    #pragma unroll
    for (int i = 0; i < 2; i++)
        #pragma unroll
        for (int j = 0; j < 4; j++) { ad[i][j] = 0ull; ax[i][j] = 0ull; }

    #pragma unroll 8
    for (int k = 0; k < 128; k++) {
        ulonglong2 A  = *(const ulonglong2*)(H1  + k * 64 + pp);
        ulonglong2 S  = *(const ulonglong2*)(H1S + k * 64 + pp);
        ulonglong2 B0 = *(const ulonglong2*)(W2s + k * 128 + cc);
        ulonglong2 B1 = *(const ulonglong2*)(W2s + k * 128 + cc + 4);
        unsigned long long b0 = B0.x, b1 = B0.y, b2 = B1.x, b3 = B1.y;
        fma2(ad[0][0], A.x, b0); fma2(ax[0][0], S.x, b0);
        fma2(ad[1][0], A.y, b0); fma2(ax[1][0], S.y, b0);
        fma2(ad[0][1], A.x, b1); fma2(ax[0][1], S.x, b1);
        fma2(ad[1][1], A.y, b1); fma2(ax[1][1], S.y, b1);
        fma2(ad[0][2], A.x, b2); fma2(ax[0][2], S.x, b2);
        fma2(ad[1][2], A.y, b2); fma2(ax[1][2], S.y, b2);
        fma2(ad[0][3], A.x, b3); fma2(ax[0][3], S.x, b3);
        fma2(ad[1][3], A.y, b3); fma2(ax[1][3], S.y, b3);
    }

    // ====== fused epilogue: out = relu(h2) @ w3, reduce across oc ======
    float part0 = 0.0f, part1 = 0.0f, part2 = 0.0f, part3 = 0.0f;
    #pragma unroll
    for (int j = 0; j < 4; j++) {
        float wa = W3s[cc + 2 * j];
        float wb = W3s[cc + 2 * j + 1];
        part0 += fmaxf(lo32(ad[0][j]), 0.0f) * wa + fmaxf(hi32(ax[0][j]), 0.0f) * wb;
        part1 += fmaxf(lo32(ax[0][j]), 0.0f) * wa + fmaxf(hi32(ad[0][j]), 0.0f) * wb;
        part2 += fmaxf(lo32(ad[1][j]), 0.0f) * wa + fmaxf(hi32(ax[1][j]), 0.0f) * wb;
        part3 += fmaxf(lo32(ax[1][j]), 0.0f) * wa + fmaxf(hi32(ad[1][j]), 0.0f) * wb;
    }
    #pragma unroll
    for (int m = 1; m < 16; m <<= 1) {
        part0 += __shfl_xor_sync(0xffffffffu, part0, m);
        part1 += __shfl_xor_sync(0xffffffffu, part1, m);
        part2 += __shfl_xor_sync(0xffffffffu, part2, m);
        part3 += __shfl_xor_sync(0xffffffffu, part3, m);
    }
    if (oc == 0) {
        const int base = blockIdx.x * PIX + pp;
        out[base + 0] = part0;
        out[base + 1] = part1;
        out[base + 2] = part2;
        out[base + 3] = part3;
    }
}

extern "C" void kernel_launch(void* const* d_in, const int* in_sizes, int n_in,
                              void* d_out, int out_size)
{
    // inputs: [0]=H(i32), [1]=W(i32), [2]=table f32[12*2^20*4],
    //         [3]=w1 f32[48*128], [4]=w2 f32[128*128], [5]=w3 f32[128]
    const float* tab = (const float*)d_in[2];
    const float* w1  = (const float*)d_in[3];
    const float* w2  = (const float*)d_in[4];
    const float* w3  = (const float*)d_in[5];
    float* out = (float*)d_out;

    cudaFuncSetAttribute(inr_fused_kernel,
                         cudaFuncAttributeMaxDynamicSharedMemorySize, SMEM_BYTES);

    const int blocks = out_size / PIX;   // 1024*1024 / 64 = 16384
    inr_fused_kernel<<<blocks, THREADS, SMEM_BYTES>>>(tab, w1, w2, w3, out);
}

// round 2
// speedup vs baseline: 2.0880x; 2.0880x over previous
#include <cuda_runtime.h>
#include <cstdint>

// TCNN_INR fused: hash-grid encoding + MLP 48->128->128->1 (bias-free, ReLU).
// R2: L1-traffic-minimized FFMA2 GEMMs.
//   - 128 pixels/CTA, 256 threads (8 warps), warp tile 64 pix x 32 cols,
//     lane tile 4 pix x 16 cols (32 FFMA2 per k per lane).
//   - B (weights) read as natural col-pairs via broadcast LDS.128 (1 wf each).
//   - A read as 4 scalar LDS.32 (stride-129 padded arrays, <=2-way conflicts),
//     duplicated into both f32x2 lanes with register packs (ALU pipe).
//   - No duplicated/swapped smem arrays (halves A-side traffic + footprint).

#define PIX       128
#define THREADS   256
#define T_MASK    ((1u << 20) - 1u)
#define LDA       129      // padded row stride (floats) for ENC / H1

__constant__ float c_scale[12] = {
    15.0f, 23.0f, 35.0f, 53.0f, 80.0f, 120.5f, 181.25f, 272.375f,
    409.0625f, 614.09375f, 921.640625f, 1382.9609375f};
__constant__ unsigned c_res[12] = {
    16u, 24u, 36u, 54u, 81u, 122u, 183u, 274u, 411u, 616u, 923u, 1384u};

// smem float offsets
#define OFF_W1   0                 // 48*128   = 6144
#define OFF_W2   6144              // 128*128  = 16384
#define OFF_W3   22528             // 128
#define OFF_ENC  22656             // 48*129   = 6192
#define OFF_H1   28848             // 128*129  = 16512
#define SMEM_FLOATS 45360
#define SMEM_BYTES  (SMEM_FLOATS * 4)   // 181440
// PART (final reduction scratch, 128*9=1152 floats) aliases ENC after GEMM1.

__device__ __forceinline__ void cp16(unsigned dst, const void* src) {
    asm volatile("cp.async.cg.shared.global [%0], [%1], 16;\n" :: "r"(dst), "l"(src));
}
__device__ __forceinline__ void fma2(unsigned long long& d,
                                     unsigned long long a,
                                     unsigned long long b) {
    asm("fma.rn.f32x2 %0, %1, %2, %0;" : "+l"(d) : "l"(a), "l"(b));
}
__device__ __forceinline__ unsigned long long dup2(float x) {
    unsigned long long r; unsigned u = __float_as_uint(x);
    asm("mov.b64 %0, {%1, %1};" : "=l"(r) : "r"(u));
    return r;
}
__device__ __forceinline__ float lo32(unsigned long long v) {
    return __uint_as_float((unsigned)v);
}
__device__ __forceinline__ float hi32(unsigned long long v) {
    return __uint_as_float((unsigned)(v >> 32));
}

extern "C" __global__ void __launch_bounds__(THREADS, 1)
inr_fused_kernel(const float* __restrict__ tab,
                 const float* __restrict__ w1,
                 const float* __restrict__ w2,
                 const float* __restrict__ w3,
                 float* __restrict__ out)
{
    extern __shared__ float sm[];
    float* W1s = sm + OFF_W1;
    float* W2s = sm + OFF_W2;
    float* W3s = sm + OFF_W3;
    float* ENC = sm + OFF_ENC;
    float* H1  = sm + OFF_H1;
    float* PART = sm + OFF_ENC;    // alias (safe: used only after GEMM1)

    const int t = threadIdx.x;

    // ---- stage weights via cp.async, overlapped with encoding ----
    {
        unsigned s1 = (unsigned)__cvta_generic_to_shared(W1s);
        for (int i = t; i < 1536; i += THREADS) cp16(s1 + i * 16, w1 + i * 4);
        unsigned s2 = (unsigned)__cvta_generic_to_shared(W2s);
        for (int i = t; i < 4096; i += THREADS) cp16(s2 + i * 16, w2 + i * 4);
        if (t < 32) {
            unsigned s3 = (unsigned)__cvta_generic_to_shared(W3s);
            cp16(s3 + t * 16, w3 + t * 4);
        }
        asm volatile("cp.async.commit_group;\n" ::: "memory");
    }

    // ---- encoding: 128 pixels x 12 levels = 1536 tasks, 6/thread ----
    {
        const int p   = t & 127;
        const int pid = blockIdx.x * PIX + p;
        const float cx = (float)(pid & 1023) * (1.0f / 1023.0f);
        const float cy = (float)(pid >> 10)  * (1.0f / 1023.0f);

        #pragma unroll
        for (int it = 0; it < 6; it++) {
            const int l = it * 2 + (t >> 7);     // warp-uniform level
            const float    sc  = c_scale[l];
            const unsigned res = c_res[l];

            float posx = fmaf(cx, sc, 0.5f);
            float fx = floorf(posx); float wx = posx - fx;
            float posy = fmaf(cy, sc, 0.5f);
            float fy = floorf(posy); float wy = posy - fy;
            unsigned px0 = (unsigned)fx, py0 = (unsigned)fy;
            unsigned px1 = min(px0 + 1u, res - 1u);
            unsigned py1 = min(py0 + 1u, res - 1u);

            unsigned i00, i10, i01, i11;
            if (l < 11) {
                i00 = px0 + py0 * res; i10 = px1 + py0 * res;
                i01 = px0 + py1 * res; i11 = px1 + py1 * res;
            } else {
                unsigned hy0 = py0 * 2654435761u, hy1 = py1 * 2654435761u;
                i00 = (px0 ^ hy0) & T_MASK; i10 = (px1 ^ hy0) & T_MASK;
                i01 = (px0 ^ hy1) & T_MASK; i11 = (px1 ^ hy1) & T_MASK;
            }

            const float4* tb = (const float4*)tab + ((size_t)l << 20);
            float4 v00 = __ldg(tb + i00);
            float4 v10 = __ldg(tb + i10);
            float4 v01 = __ldg(tb + i01);
            float4 v11 = __ldg(tb + i11);

            float w00 = (1.0f - wx) * (1.0f - wy);
            float w10 = wx * (1.0f - wy);
            float w01 = (1.0f - wx) * wy;
            float w11 = wx * wy;

            float fxv = v00.x * w00 + v10.x * w10 + v01.x * w01 + v11.x * w11;
            float fyv = v00.y * w00 + v10.y * w10 + v01.y * w01 + v11.y * w11;
            float fzv = v00.z * w00 + v10.z * w10 + v01.z * w01 + v11.z * w11;
            float fwv = v00.w * w00 + v10.w * w10 + v01.w * w01 + v11.w * w11;

            const int r = 4 * l;
            ENC[(r + 0) * LDA + p] = fxv;
            ENC[(r + 1) * LDA + p] = fyv;
            ENC[(r + 2) * LDA + p] = fzv;
            ENC[(r + 3) * LDA + p] = fwv;
        }
    }

    asm volatile("cp.async.wait_group 0;\n" ::: "memory");
    __syncthreads();

    // ---- GEMM decomposition ----
    // warp w: wp = w&1 (pixel half), wc = w>>1 (col quarter)
    // lane l: pg = l&15 -> pixels wp*64 + pg*4 .. +3 ; cg = l>>4 -> cols wc*32+cg*16
    const int w  = t >> 5;
    const int l  = t & 31;
    const int p0 = (w & 1) * 64 + (l & 15) * 4;
    const int cc = (w >> 1) * 32 + (l >> 4) * 16;

    unsigned long long acc[4][8];

    // ================= GEMM1: h1 = relu(enc @ w1), K = 48 =================
    #pragma unroll
    for (int i = 0; i < 4; i++)
        #pragma unroll
        for (int j = 0; j < 8; j++) acc[i][j] = 0ull;

    #pragma unroll 4
    for (int k = 0; k < 48; k++) {
        const float* a = ENC + k * LDA + p0;
        unsigned long long A0 = dup2(a[0]);
        unsigned long long A1 = dup2(a[1]);
        unsigned long long A2 = dup2(a[2]);
        unsigned long long A3 = dup2(a[3]);
        const float* brow = W1s + k * 128 + cc;
        ulonglong2 B01 = *(const ulonglong2*)(brow);
        ulonglong2 B23 = *(const ulonglong2*)(brow + 4);
        ulonglong2 B45 = *(const ulonglong2*)(brow + 8);
        ulonglong2 B67 = *(const ulonglong2*)(brow + 12);
        unsigned long long b[8] = {B01.x, B01.y, B23.x, B23.y,
                                   B45.x, B45.y, B67.x, B67.y};
        #pragma unroll
        for (int j = 0; j < 8; j++) {
            fma2(acc[0][j], A0, b[j]);
            fma2(acc[1][j], A1, b[j]);
            fma2(acc[2][j], A2, b[j]);
            fma2(acc[3][j], A3, b[j]);
        }
    }

    // relu + scatter h1 into k-major [c][p], stride LDA
    #pragma unroll
    for (int i = 0; i < 4; i++)
        #pragma unroll
        for (int j = 0; j < 8; j++) {
            H1[(cc + 2 * j    ) * LDA + p0 + i] = fmaxf(lo32(acc[i][j]), 0.0f);
            H1[(cc + 2 * j + 1) * LDA + p0 + i] = fmaxf(hi32(acc[i][j]), 0.0f);
        }
    __syncthreads();

    // ================= GEMM2: h2 = relu(h1 @ w2), K = 128 ==================
    #pragma unroll
    for (int i = 0; i < 4; i++)
        #pragma unroll
        for (int j = 0; j < 8; j++) acc[i][j] = 0ull;

    #pragma unroll 4
    for (int k = 0; k < 128; k++) {
        const float* a = H1 + k * LDA + p0;
        unsigned long long A0 = dup2(a[0]);
        unsigned long long A1 = dup2(a[1]);
        unsigned long long A2 = dup2(a[2]);
        unsigned long long A3 = dup2(a[3]);
        const float* brow = W2s + k * 128 + cc;
        ulonglong2 B01 = *(const ulonglong2*)(brow);
        ulonglong2 B23 = *(const ulonglong2*)(brow + 4);
        ulonglong2 B45 = *(const ulonglong2*)(brow + 8);
        ulonglong2 B67 = *(const ulonglong2*)(brow + 12);
        unsigned long long b[8] = {B01.x, B01.y, B23.x, B23.y,
                                   B45.x, B45.y, B67.x, B67.y};
        #pragma unroll
        for (int j = 0; j < 8; j++) {
            fma2(acc[0][j], A0, b[j]);
            fma2(acc[1][j], A1, b[j]);
            fma2(acc[2][j], A2, b[j]);
            fma2(acc[3][j], A3, b[j]);
        }
    }

    // ====== GEMM3 fused: out[p] = sum_c relu(h2[p][c]) * w3[c] ======
    float part[4] = {0.0f, 0.0f, 0.0f, 0.0f};
    #pragma unroll
    for (int j = 0; j < 8; j++) {
        float wa = W3s[cc + 2 * j];
        float wb = W3s[cc + 2 * j + 1];
        #pragma unroll
        for (int i = 0; i < 4; i++) {
            part[i] += fmaxf(lo32(acc[i][j]), 0.0f) * wa
                     + fmaxf(hi32(acc[i][j]), 0.0f) * wb;
        }
    }
    // 8 partials per pixel: r = wc*2 + cg
    {
        const int r = (w >> 1) * 2 + (l >> 4);
        #pragma unroll
        for (int i = 0; i < 4; i++)
            PART[(p0 + i) * 9 + r] = part[i];
    }
    __syncthreads();

    if (t < PIX) {
        const float* q = PART + t * 9;
        float s = ((q[0] + q[1]) + (q[2] + q[3]))
                + ((q[4] + q[5]) + (q[6] + q[7]));
        out[blockIdx.x * PIX + t] = s;
    }
}

extern "C" void kernel_launch(void* const* d_in, const int* in_sizes, int n_in,
                              void* d_out, int out_size)
{
    // inputs: [0]=H, [1]=W, [2]=table f32[12*2^20*4],
    //         [3]=w1 f32[48*128], [4]=w2 f32[128*128], [5]=w3 f32[128]
    const float* tab = (const float*)d_in[2];
    const float* w1  = (const float*)d_in[3];
    const float* w2  = (const float*)d_in[4];
    const float* w3  = (const float*)d_in[5];
    float* out = (float*)d_out;

    cudaFuncSetAttribute(inr_fused_kernel,
                         cudaFuncAttributeMaxDynamicSharedMemorySize, SMEM_BYTES);

    const int blocks = out_size / PIX;   // 1024*1024 / 128 = 8192
    inr_fused_kernel<<<blocks, THREADS, SMEM_BYTES>>>(tab, w1, w2, w3, out);
}

// round 5
// speedup vs baseline: 4.6332x; 2.2190x over previous
#include <cuda_runtime.h>
#include <cuda_bf16.h>
#include <cstdint>

// TCNN_INR fused, R4: hash-grid encoding + MLP 48->128->128->1 via legacy
// mma.sync m16n8k16 bf16 (HMMA fallback path; tcgen05 unavailable: harness
// PTX targets plain sm_103). 2-term bf16 compensation per GEMM:
//   D = Ah*Bh + Ah*Bl + Al*Bh  (fp32 accum), dropped term ~2^-16.
// CTA = 128 pixels, 256 threads (8 warps). Warp tile 64 pix x 32 cols
// (warps: 2 M-halves x 4 N-quarters; frags: 4 m16 x 4 n8).
// Fragments loaded with plain LDS.32 from pad-tuned row-major smem
// (112 B rows for K<=56, 272 B rows for K=128 -> conflict-free gathers).

#define THREADS 256
#define PIX     128
#define T_MASK  ((1u << 20) - 1u)

#define P1  112   // row stride bytes, A1/B1 (56 bf16)
#define P2  272   // row stride bytes, A2/B2 (136 bf16)

__constant__ float c_scale[12] = {
    15.0f, 23.0f, 35.0f, 53.0f, 80.0f, 120.5f, 181.25f, 272.375f,
    409.0625f, 614.09375f, 921.640625f, 1382.9609375f};
__constant__ unsigned c_res[12] = {
    16u, 24u, 36u, 54u, 81u, 122u, 183u, 274u, 411u, 616u, 923u, 1384u};

// prep output: transposed B[n][k] hi/lo, padded rows (56 / 136 bf16)
__device__ __nv_bfloat16 g_b1hi[128 * 56];
__device__ __nv_bfloat16 g_b1lo[128 * 56];
__device__ __nv_bfloat16 g_b2hi[128 * 136];
__device__ __nv_bfloat16 g_b2lo[128 * 136];

// ---- smem byte offsets ----
#define SO_W3    0          // 512 B fp32
#define SO_PARTS 512        // 128*4*4 = 2048 B
#define SO_A1HI  2560       // 128*112 = 14336
#define SO_A1LO  16896
#define SO_B1HI  31232
#define SO_B1LO  45568
#define SO_A2HI  59904      // 128*272 = 34816
#define SO_A2LO  94720
#define SO_B2HI  129536
#define SO_B2LO  164352
#define SMEM_BYTES 199168

static __device__ __forceinline__ void cp16(uint32_t dst, const void* src) {
    asm volatile("cp.async.cg.shared.global [%0], [%1], 16;\n" :: "r"(dst), "l"(src));
}
static __device__ __forceinline__ uint32_t smem_u32(const void* p) {
    uint32_t a;
    asm("{ .reg .u64 t; cvta.to.shared.u64 t, %1; cvt.u32.u64 %0, t; }"
        : "=r"(a) : "l"(p));
    return a;
}
static __device__ __forceinline__ uint32_t pack2(float lo, float hi) {
    uint32_t r;
    asm("cvt.rn.bf16x2.f32 %0, %1, %2;" : "=r"(r) : "f"(hi), "f"(lo));
    return r;
}
static __device__ __forceinline__ void split1(float v, float& hi, float& lo) {
    __nv_bfloat16 h = __float2bfloat16(v);
    hi = __bfloat162float(h);
    lo = v - hi;
}
static __device__ __forceinline__ void mma16816(float* c,
        uint32_t a0, uint32_t a1, uint32_t a2, uint32_t a3,
        uint32_t b0, uint32_t b1) {
    asm volatile(
        "mma.sync.aligned.m16n8k16.row.col.f32.bf16.bf16.f32 "
        "{%0,%1,%2,%3}, {%4,%5,%6,%7}, {%8,%9}, {%0,%1,%2,%3};"
        : "+f"(c[0]), "+f"(c[1]), "+f"(c[2]), "+f"(c[3])
        : "r"(a0), "r"(a1), "r"(a2), "r"(a3), "r"(b0), "r"(b1));
}
static __device__ __forceinline__ uint32_t lds32(const char* p) {
    return *(const uint32_t*)p;
}

// ---- prep: transpose + bf16-split weights into padded globals ----
__global__ void prep_kernel(const float* __restrict__ w1,
                            const float* __restrict__ w2) {
    int i = blockIdx.x * blockDim.x + threadIdx.x;
    if (i < 128 * 56) {
        int n = i / 56, k = i % 56;
        float v = (k < 48) ? w1[k * 128 + n] : 0.0f;
        float hi, lo; split1(v, hi, lo);
        g_b1hi[i] = __float2bfloat16(hi);
        g_b1lo[i] = __float2bfloat16(lo);
    }
    if (i < 128 * 136) {
        int n = i / 136, k = i % 136;
        float v = (k < 128) ? w2[k * 128 + n] : 0.0f;
        float hi, lo; split1(v, hi, lo);
        g_b2hi[i] = __float2bfloat16(hi);
        g_b2lo[i] = __float2bfloat16(lo);
    }
}

extern "C" __global__ void __launch_bounds__(THREADS, 1)
inr_mma_kernel(const float* __restrict__ tab,
               const float* __restrict__ w3g,
               float* __restrict__ out)
{
    extern __shared__ char sm[];
    const uint32_t sb = smem_u32(sm);
    const int t  = threadIdx.x;
    const int w  = t >> 5;
    const int ln = t & 31;
    const int qr = ln >> 2;          // lane row within fragment group (0..7)
    const int qc = ln & 3;           // lane quad column (0..3)
    const int wm = w & 1;            // M half (0,1)
    const int wn = w >> 1;           // N quarter (0..3)

    // ---- stage weights via cp.async ----
    for (int i = t; i < 896; i += THREADS) {           // B1: 128 rows x 7 chunks
        int row = i / 7, ch = i % 7;
        uint32_t off = (uint32_t)(row * P1 + ch * 16);
        cp16(sb + SO_B1HI + off, g_b1hi + row * 56 + ch * 8);
        cp16(sb + SO_B1LO + off, g_b1lo + row * 56 + ch * 8);
    }
    for (int i = t; i < 2176; i += THREADS) {          // B2: 128 rows x 17 chunks
        int row = i / 17, ch = i % 17;
        uint32_t off = (uint32_t)(row * P2 + ch * 16);
        cp16(sb + SO_B2HI + off, g_b2hi + row * 136 + ch * 8);
        cp16(sb + SO_B2LO + off, g_b2lo + row * 136 + ch * 8);
    }
    if (t < 32) cp16(sb + SO_W3 + t * 16, w3g + t * 4);
    asm volatile("cp.async.commit_group;\n" ::: "memory");

    // ---- encoding: 128 px x 12 levels; A1 hi/lo bf16, row-major [p][k] ----
    {
        const int p   = t & 127;
        const int pid = blockIdx.x * PIX + p;
        const float cx = (float)(pid & 1023) * (1.0f / 1023.0f);
        const float cy = (float)(pid >> 10)  * (1.0f / 1023.0f);

        #pragma unroll
        for (int it = 0; it < 6; it++) {
            const int lv = it * 2 + (t >> 7);
            const float    sc  = c_scale[lv];
            const unsigned res = c_res[lv];

            float posx = fmaf(cx, sc, 0.5f);
            float fx = floorf(posx); float wx = posx - fx;
            float posy = fmaf(cy, sc, 0.5f);
            float fy = floorf(posy); float wy = posy - fy;
            unsigned px0 = (unsigned)fx, py0 = (unsigned)fy;
            unsigned px1 = min(px0 + 1u, res - 1u);
            unsigned py1 = min(py0 + 1u, res - 1u);

            unsigned i00, i10, i01, i11;
            if (lv < 11) {
                i00 = px0 + py0 * res; i10 = px1 + py0 * res;
                i01 = px0 + py1 * res; i11 = px1 + py1 * res;
            } else {
                unsigned hy0 = py0 * 2654435761u, hy1 = py1 * 2654435761u;
                i00 = (px0 ^ hy0) & T_MASK; i10 = (px1 ^ hy0) & T_MASK;
                i01 = (px0 ^ hy1) & T_MASK; i11 = (px1 ^ hy1) & T_MASK;
            }

            const float4* tb = (const float4*)tab + ((size_t)lv << 20);
            float4 v00 = __ldg(tb + i00);
            float4 v10 = __ldg(tb + i10);
            float4 v01 = __ldg(tb + i01);
            float4 v11 = __ldg(tb + i11);

            float w00 = (1.0f - wx) * (1.0f - wy);
            float w10 = wx * (1.0f - wy);
            float w01 = (1.0f - wx) * wy;
            float w11 = wx * wy;

            float f0 = v00.x * w00 + v10.x * w10 + v01.x * w01 + v11.x * w11;
            float f1 = v00.y * w00 + v10.y * w10 + v01.y * w01 + v11.y * w11;
            float f2 = v00.z * w00 + v10.z * w10 + v01.z * w01 + v11.z * w11;
            float f3 = v00.w * w00 + v10.w * w10 + v01.w * w01 + v11.w * w11;

            float h0, l0, h1, l1, h2, l2, h3, l3;
            split1(f0, h0, l0); split1(f1, h1, l1);
            split1(f2, h2, l2); split1(f3, h3, l3);

            uint32_t off = (uint32_t)(p * P1 + lv * 8);
            *(uint2*)(sm + SO_A1HI + off) = make_uint2(pack2(h0, h1), pack2(h2, h3));
            *(uint2*)(sm + SO_A1LO + off) = make_uint2(pack2(l0, l1), pack2(l2, l3));
        }
    }

    asm volatile("cp.async.wait_group 0;\n" ::: "memory");
    __syncthreads();

    float acc[4][4][4];

    // ================= GEMM1: D1 = enc @ w1, K = 48 (3 k-steps) =============
    #pragma unroll
    for (int i = 0; i < 4; i++)
        #pragma unroll
        for (int j = 0; j < 4; j++)
            #pragma unroll
            for (int q = 0; q < 4; q++) acc[i][j][q] = 0.0f;

    {
        // per-thread base addresses
        const char* aH = sm + SO_A1HI + (wm * 64 + qr) * P1 + qc * 4;
        const char* aL = sm + SO_A1LO + (wm * 64 + qr) * P1 + qc * 4;
        const char* bH = sm + SO_B1HI + (wn * 32 + qr) * P1 + qc * 4;
        const char* bL = sm + SO_B1LO + (wn * 32 + qr) * P1 + qc * 4;

        #pragma unroll
        for (int s = 0; s < 3; s++) {
            const int ko = s * 32;   // bytes
            uint32_t Ah[4][4], Al[4][4];
            #pragma unroll
            for (int mf = 0; mf < 4; mf++) {
                const int ro = mf * 16 * P1 + ko;
                Ah[mf][0] = lds32(aH + ro);
                Ah[mf][1] = lds32(aH + ro + 8 * P1);
                Ah[mf][2] = lds32(aH + ro + 16);
                Ah[mf][3] = lds32(aH + ro + 8 * P1 + 16);
                Al[mf][0] = lds32(aL + ro);
                Al[mf][1] = lds32(aL + ro + 8 * P1);
                Al[mf][2] = lds32(aL + ro + 16);
                Al[mf][3] = lds32(aL + ro + 8 * P1 + 16);
            }
            uint32_t Bh[4][2], Bl[4][2];
            #pragma unroll
            for (int nf = 0; nf < 4; nf++) {
                const int no = nf * 8 * P1 + ko;
                Bh[nf][0] = lds32(bH + no);
                Bh[nf][1] = lds32(bH + no + 16);
                Bl[nf][0] = lds32(bL + no);
                Bl[nf][1] = lds32(bL + no + 16);
            }
            #pragma unroll
            for (int mf = 0; mf < 4; mf++)
                #pragma unroll
                for (int nf = 0; nf < 4; nf++) {
                    float* c = acc[mf][nf];
                    mma16816(c, Ah[mf][0], Ah[mf][1], Ah[mf][2], Ah[mf][3],
                             Bh[nf][0], Bh[nf][1]);
                    mma16816(c, Ah[mf][0], Ah[mf][1], Ah[mf][2], Ah[mf][3],
                             Bl[nf][0], Bl[nf][1]);
                    mma16816(c, Al[mf][0], Al[mf][1], Al[mf][2], Al[mf][3],
                             Bh[nf][0], Bh[nf][1]);
                }
        }
    }

    // ---- epilogue1: relu + split -> A2 [p][c] hi/lo ----
    {
        char* dh = sm + SO_A2HI;
        char* dl = sm + SO_A2LO;
        const int colb = wn * 32 + qc * 2;
        #pragma unroll
        for (int mf = 0; mf < 4; mf++) {
            const int r0 = wm * 64 + mf * 16 + qr;
            #pragma unroll
            for (int nf = 0; nf < 4; nf++) {
                const int col = colb + nf * 8;
                float v0 = fmaxf(acc[mf][nf][0], 0.0f);
                float v1 = fmaxf(acc[mf][nf][1], 0.0f);
                float v2 = fmaxf(acc[mf][nf][2], 0.0f);
                float v3 = fmaxf(acc[mf][nf][3], 0.0f);
                float h0, l0, h1, l1, h2, l2, h3, l3;
                split1(v0, h0, l0); split1(v1, h1, l1);
                split1(v2, h2, l2); split1(v3, h3, l3);
                *(uint32_t*)(dh + r0 * P2 + col * 2)       = pack2(h0, h1);
                *(uint32_t*)(dl + r0 * P2 + col * 2)       = pack2(l0, l1);
                *(uint32_t*)(dh + (r0 + 8) * P2 + col * 2) = pack2(h2, h3);
                *(uint32_t*)(dl + (r0 + 8) * P2 + col * 2) = pack2(l2, l3);
            }
        }
    }
    __syncthreads();

    // ================= GEMM2: D2 = h1 @ w2, K = 128 (8 k-steps) =============
    #pragma unroll
    for (int i = 0; i < 4; i++)
        #pragma unroll
        for (int j = 0; j < 4; j++)
            #pragma unroll
            for (int q = 0; q < 4; q++) acc[i][j][q] = 0.0f;

    {
        const char* aH = sm + SO_A2HI + (wm * 64 + qr) * P2 + qc * 4;
        const char* aL = sm + SO_A2LO + (wm * 64 + qr) * P2 + qc * 4;
        const char* bH = sm + SO_B2HI + (wn * 32 + qr) * P2 + qc * 4;
        const char* bL = sm + SO_B2LO + (wn * 32 + qr) * P2 + qc * 4;

        #pragma unroll 2
        for (int s = 0; s < 8; s++) {
            const int ko = s * 32;
            uint32_t Ah[4][4], Al[4][4];
            #pragma unroll
            for (int mf = 0; mf < 4; mf++) {
                const int ro = mf * 16 * P2 + ko;
                Ah[mf][0] = lds32(aH + ro);
                Ah[mf][1] = lds32(aH + ro + 8 * P2);
                Ah[mf][2] = lds32(aH + ro + 16);
                Ah[mf][3] = lds32(aH + ro + 8 * P2 + 16);
                Al[mf][0] = lds32(aL + ro);
                Al[mf][1] = lds32(aL + ro + 8 * P2);
                Al[mf][2] = lds32(aL + ro + 16);
                Al[mf][3] = lds32(aL + ro + 8 * P2 + 16);
            }
            uint32_t Bh[4][2], Bl[4][2];
            #pragma unroll
            for (int nf = 0; nf < 4; nf++) {
                const int no = nf * 8 * P2 + ko;
                Bh[nf][0] = lds32(bH + no);
                Bh[nf][1] = lds32(bH + no + 16);
                Bl[nf][0] = lds32(bL + no);
                Bl[nf][1] = lds32(bL + no + 16);
            }
            #pragma unroll
            for (int mf = 0; mf < 4; mf++)
                #pragma unroll
                for (int nf = 0; nf < 4; nf++) {
                    float* c = acc[mf][nf];
                    mma16816(c, Ah[mf][0], Ah[mf][1], Ah[mf][2], Ah[mf][3],
                             Bh[nf][0], Bh[nf][1]);
                    mma16816(c, Ah[mf][0], Ah[mf][1], Ah[mf][2], Ah[mf][3],
                             Bl[nf][0], Bl[nf][1]);
                    mma16816(c, Al[mf][0], Al[mf][1], Al[mf][2], Al[mf][3],
                             Bh[nf][0], Bh[nf][1]);
                }
        }
    }

    // ---- epilogue2: out[p] = sum_c relu(D2[p][c]) * w3[c], quad-reduce ----
    {
        const float* w3s = (const float*)(sm + SO_W3);
        float* parts = (float*)(sm + SO_PARTS);
        const int colb = wn * 32 + qc * 2;
        #pragma unroll
        for (int mf = 0; mf < 4; mf++) {
            float p0 = 0.0f, p1 = 0.0f;
            #pragma unroll
            for (int nf = 0; nf < 4; nf++) {
                const int col = colb + nf * 8;
                float wa = w3s[col], wb = w3s[col + 1];
                p0 += fmaxf(acc[mf][nf][0], 0.0f) * wa
                    + fmaxf(acc[mf][nf][1], 0.0f) * wb;
                p1 += fmaxf(acc[mf][nf][2], 0.0f) * wa
                    + fmaxf(acc[mf][nf][3], 0.0f) * wb;
            }
            p0 += __shfl_xor_sync(0xffffffffu, p0, 1);
            p0 += __shfl_xor_sync(0xffffffffu, p0, 2);
            p1 += __shfl_xor_sync(0xffffffffu, p1, 1);
            p1 += __shfl_xor_sync(0xffffffffu, p1, 2);
            if (qc == 0) {
                const int r0 = wm * 64 + mf * 16 + qr;
                parts[r0 * 4 + wn]       = p0;
                parts[(r0 + 8) * 4 + wn] = p1;
            }
        }
    }
    __syncthreads();

    if (t < PIX) {
        const float* q = (const float*)(sm + SO_PARTS) + t * 4;
        out[blockIdx.x * PIX + t] = (q[0] + q[1]) + (q[2] + q[3]);
    }
}

extern "C" void kernel_launch(void* const* d_in, const int* in_sizes, int n_in,
                              void* d_out, int out_size)
{
    // inputs: [0]=H, [1]=W, [2]=table f32[12*2^20*4],
    //         [3]=w1 f32[48*128], [4]=w2 f32[128*128], [5]=w3 f32[128]
    const float* tab = (const float*)d_in[2];
    const float* w1  = (const float*)d_in[3];
    const float* w2  = (const float*)d_in[4];
    const float* w3  = (const float*)d_in[5];
    float* out = (float*)d_out;

    cudaFuncSetAttribute(inr_mma_kernel,
                         cudaFuncAttributeMaxDynamicSharedMemorySize, SMEM_BYTES);

    prep_kernel<<<68, 256>>>(w1, w2);    // 17408 threads cover both tables
    const int blocks = out_size / PIX;   // 8192
    inr_mma_kernel<<<blocks, THREADS, SMEM_BYTES>>>(tab, w3, out);
}

// round 9
// speedup vs baseline: 4.6387x; 1.0012x over previous
#include <cuda_runtime.h>
#include <cuda_bf16.h>
#include <cstdint>

// TCNN_INR fused, R5: persistent-CTA pipelined version of R4.
//   - mma.sync m16n8k16 bf16, 2-term compensation (D = Ah*Bh + Ah*Bl + Al*Bh)
//   - persistent CTAs (grid=160) + dynamic tile counter: weights staged once
//   - encoding of tile i+1 interleaved into GEMM2 k-loop of tile i so the
//     hash-table gathers (LDG latency) hide behind tensor-pipe HMMAs.

#define THREADS 256
#define PIX     128
#define T_MASK  ((1u << 20) - 1u)

#define P1  112   // row stride bytes, A1/B1 (56 bf16)
#define P2  272   // row stride bytes, A2/B2 (136 bf16)

__constant__ float c_scale[12] = {
    15.0f, 23.0f, 35.0f, 53.0f, 80.0f, 120.5f, 181.25f, 272.375f,
    409.0625f, 614.09375f, 921.640625f, 1382.9609375f};
__constant__ unsigned c_res[12] = {
    16u, 24u, 36u, 54u, 81u, 122u, 183u, 274u, 411u, 616u, 923u, 1384u};

// prep output: transposed B[n][k] hi/lo, padded rows (56 / 136 bf16)
__device__ __nv_bfloat16 g_b1hi[128 * 56];
__device__ __nv_bfloat16 g_b1lo[128 * 56];
__device__ __nv_bfloat16 g_b2hi[128 * 136];
__device__ __nv_bfloat16 g_b2lo[128 * 136];
__device__ unsigned g_ctr;          // dynamic tile counter

// ---- smem byte offsets ----
#define SO_W3    0          // 512 B fp32
#define SO_PARTS 512        // 128*4*4 = 2048 B
#define SO_A1HI  2560       // 128*112 = 14336
#define SO_A1LO  16896
#define SO_B1HI  31232
#define SO_B1LO  45568
#define SO_A2HI  59904      // 128*272 = 34816
#define SO_A2LO  94720
#define SO_B2HI  129536
#define SO_B2LO  164352
#define SMEM_BYTES 199168

static __device__ __forceinline__ void cp16(uint32_t dst, const void* src) {
    asm volatile("cp.async.cg.shared.global [%0], [%1], 16;\n" :: "r"(dst), "l"(src));
}
static __device__ __forceinline__ uint32_t smem_u32(const void* p) {
    uint32_t a;
    asm("{ .reg .u64 t; cvta.to.shared.u64 t, %1; cvt.u32.u64 %0, t; }"
        : "=r"(a) : "l"(p));
    return a;
}
static __device__ __forceinline__ uint32_t pack2(float lo, float hi) {
    uint32_t r;
    asm("cvt.rn.bf16x2.f32 %0, %1, %2;" : "=r"(r) : "f"(hi), "f"(lo));
    return r;
}
static __device__ __forceinline__ void split1(float v, float& hi, float& lo) {
    __nv_bfloat16 h = __float2bfloat16(v);
    hi = __bfloat162float(h);
    lo = v - hi;
}
static __device__ __forceinline__ void mma16816(float* c,
        uint32_t a0, uint32_t a1, uint32_t a2, uint32_t a3,
        uint32_t b0, uint32_t b1) {
    asm volatile(
        "mma.sync.aligned.m16n8k16.row.col.f32.bf16.bf16.f32 "
        "{%0,%1,%2,%3}, {%4,%5,%6,%7}, {%8,%9}, {%0,%1,%2,%3};"
        : "+f"(c[0]), "+f"(c[1]), "+f"(c[2]), "+f"(c[3])
        : "r"(a0), "r"(a1), "r"(a2), "r"(a3), "r"(b0), "r"(b1));
}
static __device__ __forceinline__ uint32_t lds32(const char* p) {
    return *(const uint32_t*)p;
}

// one encoding task: pixel p of tile (global pid), level lv -> A1 hi/lo
static __device__ __forceinline__ void enc_one(const float* __restrict__ tab,
                                               char* sm, int pid, int lv, int p)
{
    const float    sc  = c_scale[lv];
    const unsigned res = c_res[lv];
    const float cx = (float)(pid & 1023) * (1.0f / 1023.0f);
    const float cy = (float)(pid >> 10)  * (1.0f / 1023.0f);

    float posx = fmaf(cx, sc, 0.5f);
    float fx = floorf(posx); float wx = posx - fx;
    float posy = fmaf(cy, sc, 0.5f);
    float fy = floorf(posy); float wy = posy - fy;
    unsigned px0 = (unsigned)fx, py0 = (unsigned)fy;
    unsigned px1 = min(px0 + 1u, res - 1u);
    unsigned py1 = min(py0 + 1u, res - 1u);

    unsigned i00, i10, i01, i11;
    if (lv < 11) {
        i00 = px0 + py0 * res; i10 = px1 + py0 * res;
        i01 = px0 + py1 * res; i11 = px1 + py1 * res;
    } else {
        unsigned hy0 = py0 * 2654435761u, hy1 = py1 * 2654435761u;
        i00 = (px0 ^ hy0) & T_MASK; i10 = (px1 ^ hy0) & T_MASK;
        i01 = (px0 ^ hy1) & T_MASK; i11 = (px1 ^ hy1) & T_MASK;
    }

    const float4* tb = (const float4*)tab + ((size_t)lv << 20);
    float4 v00 = __ldg(tb + i00);
    float4 v10 = __ldg(tb + i10);
    float4 v01 = __ldg(tb + i01);
    float4 v11 = __ldg(tb + i11);

    float w00 = (1.0f - wx) * (1.0f - wy);
    float w10 = wx * (1.0f - wy);
    float w01 = (1.0f - wx) * wy;
    float w11 = wx * wy;

    float f0 = v00.x * w00 + v10.x * w10 + v01.x * w01 + v11.x * w11;
    float f1 = v00.y * w00 + v10.y * w10 + v01.y * w01 + v11.y * w11;
    float f2 = v00.z * w00 + v10.z * w10 + v01.z * w01 + v11.z * w11;
    float f3 = v00.w * w00 + v10.w * w10 + v01.w * w01 + v11.w * w11;

    float h0, l0, h1, l1, h2, l2, h3, l3;
    split1(f0, h0, l0); split1(f1, h1, l1);
    split1(f2, h2, l2); split1(f3, h3, l3);

    uint32_t off = (uint32_t)(p * P1 + lv * 8);
    *(uint2*)(sm + SO_A1HI + off) = make_uint2(pack2(h0, h1), pack2(h2, h3));
    *(uint2*)(sm + SO_A1LO + off) = make_uint2(pack2(l0, l1), pack2(l2, l3));
}

// ---- prep: transpose + bf16-split weights; reset tile counter ----
__global__ void prep_kernel(const float* __restrict__ w1,
                            const float* __restrict__ w2) {
    int i = blockIdx.x * blockDim.x + threadIdx.x;
    if (i == 0) g_ctr = 0u;
    if (i < 128 * 56) {
        int n = i / 56, k = i % 56;
        float v = (k < 48) ? w1[k * 128 + n] : 0.0f;
        float hi, lo; split1(v, hi, lo);
        g_b1hi[i] = __float2bfloat16(hi);
        g_b1lo[i] = __float2bfloat16(lo);
    }
    if (i < 128 * 136) {
        int n = i / 136, k = i % 136;
        float v = (k < 128) ? w2[k * 128 + n] : 0.0f;
        float hi, lo; split1(v, hi, lo);
        g_b2hi[i] = __float2bfloat16(hi);
        g_b2lo[i] = __float2bfloat16(lo);
    }
}

extern "C" __global__ void __launch_bounds__(THREADS, 1)
inr_mma_kernel(const float* __restrict__ tab,
               const float* __restrict__ w3g,
               float* __restrict__ out,
               int NT)
{
    extern __shared__ char sm[];
    __shared__ unsigned sh_tile;
    const uint32_t sb = smem_u32(sm);
    const int t  = threadIdx.x;
    const int w  = t >> 5;
    const int ln = t & 31;
    const int qr = ln >> 2;
    const int qc = ln & 3;
    const int wm = w & 1;
    const int wn = w >> 1;
    const int p  = t & 127;
    const int lvh = t >> 7;          // level-half selector for encoding

    // ---- stage weights via cp.async (once per persistent CTA) ----
    for (int i = t; i < 896; i += THREADS) {
        int row = i / 7, ch = i % 7;
        uint32_t off = (uint32_t)(row * P1 + ch * 16);
        cp16(sb + SO_B1HI + off, g_b1hi + row * 56 + ch * 8);
        cp16(sb + SO_B1LO + off, g_b1lo + row * 56 + ch * 8);
    }
    for (int i = t; i < 2176; i += THREADS) {
        int row = i / 17, ch = i % 17;
        uint32_t off = (uint32_t)(row * P2 + ch * 16);
        cp16(sb + SO_B2HI + off, g_b2hi + row * 136 + ch * 8);
        cp16(sb + SO_B2LO + off, g_b2lo + row * 136 + ch * 8);
    }
    if (t < 32) cp16(sb + SO_W3 + t * 16, w3g + t * 4);
    asm volatile("cp.async.commit_group;\n" ::: "memory");

    // ---- grab first tile + prologue encoding ----
    if (t == 0) sh_tile = atomicAdd(&g_ctr, 1u);
    __syncthreads();
    unsigned cur = sh_tile;
    if (cur >= (unsigned)NT) return;

    #pragma unroll
    for (int it = 0; it < 6; it++)
        enc_one(tab, sm, (int)cur * PIX + p, it * 2 + lvh, p);

    asm volatile("cp.async.wait_group 0;\n" ::: "memory");
    __syncthreads();

    float acc[4][4][4];

    while (true) {
        // ================= GEMM1: K = 48 (3 k-steps), 3-term ================
        #pragma unroll
        for (int i = 0; i < 4; i++)
            #pragma unroll
            for (int j = 0; j < 4; j++)
                #pragma unroll
                for (int q = 0; q < 4; q++) acc[i][j][q] = 0.0f;

        {
            const char* aH = sm + SO_A1HI + (wm * 64 + qr) * P1 + qc * 4;
            const char* aL = sm + SO_A1LO + (wm * 64 + qr) * P1 + qc * 4;
            const char* bH = sm + SO_B1HI + (wn * 32 + qr) * P1 + qc * 4;
            const char* bL = sm + SO_B1LO + (wn * 32 + qr) * P1 + qc * 4;

            #pragma unroll
            for (int s = 0; s < 3; s++) {
                const int ko = s * 32;
                uint32_t Ah[4][4], Al[4][4];
                #pragma unroll
                for (int mf = 0; mf < 4; mf++) {
                    const int ro = mf * 16 * P1 + ko;
                    Ah[mf][0] = lds32(aH + ro);
                    Ah[mf][1] = lds32(aH + ro + 8 * P1);
                    Ah[mf][2] = lds32(aH + ro + 16);
                    Ah[mf][3] = lds32(aH + ro + 8 * P1 + 16);
                    Al[mf][0] = lds32(aL + ro);
                    Al[mf][1] = lds32(aL + ro + 8 * P1);
                    Al[mf][2] = lds32(aL + ro + 16);
                    Al[mf][3] = lds32(aL + ro + 8 * P1 + 16);
                }
                uint32_t Bh[4][2], Bl[4][2];
                #pragma unroll
                for (int nf = 0; nf < 4; nf++) {
                    const int no = nf * 8 * P1 + ko;
                    Bh[nf][0] = lds32(bH + no);
                    Bh[nf][1] = lds32(bH + no + 16);
                    Bl[nf][0] = lds32(bL + no);
                    Bl[nf][1] = lds32(bL + no + 16);
                }
                #pragma unroll
                for (int mf = 0; mf < 4; mf++)
                    #pragma unroll
                    for (int nf = 0; nf < 4; nf++) {
                        float* c = acc[mf][nf];
                        mma16816(c, Ah[mf][0], Ah[mf][1], Ah[mf][2], Ah[mf][3],
                                 Bh[nf][0], Bh[nf][1]);
                        mma16816(c, Ah[mf][0], Ah[mf][1], Ah[mf][2], Ah[mf][3],
                                 Bl[nf][0], Bl[nf][1]);
                        mma16816(c, Al[mf][0], Al[mf][1], Al[mf][2], Al[mf][3],
                                 Bh[nf][0], Bh[nf][1]);
                    }
            }
        }

        // ---- epilogue1: relu + split -> A2 ----
        {
            char* dh = sm + SO_A2HI;
            char* dl = sm + SO_A2LO;
            const int colb = wn * 32 + qc * 2;
            #pragma unroll
            for (int mf = 0; mf < 4; mf++) {
                const int r0 = wm * 64 + mf * 16 + qr;
                #pragma unroll
                for (int nf = 0; nf < 4; nf++) {
                    const int col = colb + nf * 8;
                    float v0 = fmaxf(acc[mf][nf][0], 0.0f);
                    float v1 = fmaxf(acc[mf][nf][1], 0.0f);
                    float v2 = fmaxf(acc[mf][nf][2], 0.0f);
                    float v3 = fmaxf(acc[mf][nf][3], 0.0f);
                    float h0, l0, h1, l1, h2, l2, h3, l3;
                    split1(v0, h0, l0); split1(v1, h1, l1);
                    split1(v2, h2, l2); split1(v3, h3, l3);
                    *(uint32_t*)(dh + r0 * P2 + col * 2)       = pack2(h0, h1);
                    *(uint32_t*)(dl + r0 * P2 + col * 2)       = pack2(l0, l1);
                    *(uint32_t*)(dh + (r0 + 8) * P2 + col * 2) = pack2(h2, h3);
                    *(uint32_t*)(dl + (r0 + 8) * P2 + col * 2) = pack2(l2, l3);
                }
            }
        }
        if (t == 0) sh_tile = atomicAdd(&g_ctr, 1u);
        __syncthreads();            // A2 ready; A1 free; sh_tile visible
        const unsigned nxt = sh_tile;
        const bool enc_next = (nxt < (unsigned)NT);

        // ====== GEMM2: K = 128 (8 k-steps) + interleaved enc(next) ======
        #pragma unroll
        for (int i = 0; i < 4; i++)
            #pragma unroll
            for (int j = 0; j < 4; j++)
                #pragma unroll
                for (int q = 0; q < 4; q++) acc[i][j][q] = 0.0f;

        {
            const char* aH = sm + SO_A2HI + (wm * 64 + qr) * P2 + qc * 4;
            const char* aL = sm + SO_A2LO + (wm * 64 + qr) * P2 + qc * 4;
            const char* bH = sm + SO_B2HI + (wn * 32 + qr) * P2 + qc * 4;
            const char* bL = sm + SO_B2LO + (wn * 32 + qr) * P2 + qc * 4;

            #pragma unroll 2
            for (int s = 0; s < 8; s++) {
                if (s < 6 && enc_next)
                    enc_one(tab, sm, (int)nxt * PIX + p, s * 2 + lvh, p);

                const int ko = s * 32;
                uint32_t Ah[4][4], Al[4][4];
                #pragma unroll
                for (int mf = 0; mf < 4; mf++) {
                    const int ro = mf * 16 * P2 + ko;
                    Ah[mf][0] = lds32(aH + ro);
                    Ah[mf][1] = lds32(aH + ro + 8 * P2);
                    Ah[mf][2] = lds32(aH + ro + 16);
                    Ah[mf][3] = lds32(aH + ro + 8 * P2 + 16);
                    Al[mf][0] = lds32(aL + ro);
                    Al[mf][1] = lds32(aL + ro + 8 * P2);
                    Al[mf][2] = lds32(aL + ro + 16);
                    Al[mf][3] = lds32(aL + ro + 8 * P2 + 16);
                }
                uint32_t Bh[4][2], Bl[4][2];
                #pragma unroll
                for (int nf = 0; nf < 4; nf++) {
                    const int no = nf * 8 * P2 + ko;
                    Bh[nf][0] = lds32(bH + no);
                    Bh[nf][1] = lds32(bH + no + 16);
                    Bl[nf][0] = lds32(bL + no);
                    Bl[nf][1] = lds32(bL + no + 16);
                }
                #pragma unroll
                for (int mf = 0; mf < 4; mf++)
                    #pragma unroll
                    for (int nf = 0; nf < 4; nf++) {
                        float* c = acc[mf][nf];
                        mma16816(c, Ah[mf][0], Ah[mf][1], Ah[mf][2], Ah[mf][3],
                                 Bh[nf][0], Bh[nf][1]);
                        mma16816(c, Ah[mf][0], Ah[mf][1], Ah[mf][2], Ah[mf][3],
                                 Bl[nf][0], Bl[nf][1]);
                        mma16816(c, Al[mf][0], Al[mf][1], Al[mf][2], Al[mf][3],
                                 Bh[nf][0], Bh[nf][1]);
                    }
            }
        }

        // ---- epilogue2: dot w3, quad-reduce -> PARTS ----
        {
            const float* w3s = (const float*)(sm + SO_W3);
            float* parts = (float*)(sm + SO_PARTS);
            const int colb = wn * 32 + qc * 2;
            #pragma unroll
            for (int mf = 0; mf < 4; mf++) {
                float p0 = 0.0f, p1 = 0.0f;
                #pragma unroll
                for (int nf = 0; nf < 4; nf++) {
                    const int col = colb + nf * 8;
                    float wa = w3s[col], wb = w3s[col + 1];
                    p0 += fmaxf(acc[mf][nf][0], 0.0f) * wa
                        + fmaxf(acc[mf][nf][1], 0.0f) * wb;
                    p1 += fmaxf(acc[mf][nf][2], 0.0f) * wa
                        + fmaxf(acc[mf][nf][3], 0.0f) * wb;
                }
                p0 += __shfl_xor_sync(0xffffffffu, p0, 1);
                p0 += __shfl_xor_sync(0xffffffffu, p0, 2);
                p1 += __shfl_xor_sync(0xffffffffu, p1, 1);
                p1 += __shfl_xor_sync(0xffffffffu, p1, 2);
                if (qc == 0) {
                    const int r0 = wm * 64 + mf * 16 + qr;
                    parts[r0 * 4 + wn]       = p0;
                    parts[(r0 + 8) * 4 + wn] = p1;
                }
            }
        }
        __syncthreads();            // PARTS ready; enc(next) A1 writes done

        if (t < PIX) {
            const float* q = (const float*)(sm + SO_PARTS) + t * 4;
            out[cur * PIX + t] = (q[0] + q[1]) + (q[2] + q[3]);
        }

        if (!enc_next) break;
        cur = nxt;
    }
}

extern "C" void kernel_launch(void* const* d_in, const int* in_sizes, int n_in,
                              void* d_out, int out_size)
{
    // inputs: [0]=H, [1]=W, [2]=table f32[12*2^20*4],
    //         [3]=w1 f32[48*128], [4]=w2 f32[128*128], [5]=w3 f32[128]
    const float* tab = (const float*)d_in[2];
    const float* w1  = (const float*)d_in[3];
    const float* w2  = (const float*)d_in[4];
    const float* w3  = (const float*)d_in[5];
    float* out = (float*)d_out;

    cudaFuncSetAttribute(inr_mma_kernel,
                         cudaFuncAttributeMaxDynamicSharedMemorySize, SMEM_BYTES);

    prep_kernel<<<68, 256>>>(w1, w2);      // also resets g_ctr
    const int NT = out_size / PIX;         // 8192 tiles
    inr_mma_kernel<<<160, THREADS, SMEM_BYTES>>>(tab, w3, out, NT);
}

// round 11
// speedup vs baseline: 10.2804x; 2.2162x over previous
#include <cuda_runtime.h>
#include <cuda_fp16.h>
#include <cstdint>

// TCNN_INR fused, R6: fp16 tensor-core MLP with activation scaling.
//   - Net is positively homogeneous: enc scaled by 2^12, output by 2^-12,
//     putting all activations in fp16 normal range.
//   - GEMM1: A (enc) split fp16 hi/lo, B (w1) single fp16 -> 2 MMAs/frag.
//   - GEMM2: both operands single fp16 -> 1 MMA/frag. 224 HMMA/warp total
//     (vs 528 in R5's bf16 3-term).
//   - A2 stored fragment-major uint4 (a0,a1,a2,a3): epi1 = 8 STS.128/thread,
//     GEMM2 A-loads = 4 LDS.128/kstep. B pre-packed as fragment uint2.
//   - smem 109KB -> 2 CTAs/SM (launch_bounds(256,2)), grid 304 persistent.

#define THREADS 256
#define PIX     128
#define T_MASK  ((1u << 20) - 1u)
#define P1      112     // A1 row stride bytes (48 fp16 = 96B padded)
#define ENC_SCALE   4096.0f
#define OUT_SCALE   (1.0f / 4096.0f)

__constant__ float c_scale[12] = {
    15.0f, 23.0f, 35.0f, 53.0f, 80.0f, 120.5f, 181.25f, 272.375f,
    409.0625f, 614.09375f, 921.640625f, 1382.9609375f};
__constant__ unsigned c_res[12] = {
    16u, 24u, 36u, 54u, 81u, 122u, 183u, 274u, 411u, 616u, 923u, 1384u};

// prep output: fragment-packed transposed weights (uint2 = {b0,b1} frags)
__device__ __align__(16) uint2 g_b1p[3 * 4 * 132];    // [s][qc][n pad 132]
__device__ __align__(16) uint2 g_b2p[8 * 4 * 132];
__device__ unsigned g_ctr;

// ---- smem byte offsets ----
#define SO_W3    0                  // 512
#define SO_PARTS 512                // 2048
#define SO_A1HI  2560               // 128*112 = 14336
#define SO_A1LO  16896              // 14336
#define SO_B1    31232              // 3*4*132*8 = 12672
#define SO_B2    43904              // 8*4*132*8 = 33792
#define SO_A2F   77696              // 8*4*66*16 = 33792
#define SMEM_BYTES 111488

#define B1OFF(s,qc,n)   (SO_B1 + ((((s)<<2)+(qc))*132 + (n))*8)
#define B2OFF(s,qc,n)   (SO_B2 + ((((s)<<2)+(qc))*132 + (n))*8)
#define A2FOFF(s,qc,rg) (SO_A2F + ((((s)<<2)+(qc))*66 + (rg))*16)

static __device__ __forceinline__ void cp16(uint32_t dst, const void* src) {
    asm volatile("cp.async.cg.shared.global [%0], [%1], 16;\n" :: "r"(dst), "l"(src));
}
static __device__ __forceinline__ uint32_t smem_u32(const void* p) {
    uint32_t a;
    asm("{ .reg .u64 t; cvta.to.shared.u64 t, %1; cvt.u32.u64 %0, t; }"
        : "=r"(a) : "l"(p));
    return a;
}
// pack two fp32 -> f16x2 word (lo = first arg)
static __device__ __forceinline__ uint32_t pk(float lo, float hi) {
    uint32_t r;
    asm("cvt.rn.f16x2.f32 %0, %1, %2;" : "=r"(r) : "f"(hi), "f"(lo));
    return r;
}
static __device__ __forceinline__ void mmah(float* c,
        uint32_t a0, uint32_t a1, uint32_t a2, uint32_t a3,
        uint32_t b0, uint32_t b1) {
    asm volatile(
        "mma.sync.aligned.m16n8k16.row.col.f32.f16.f16.f32 "
        "{%0,%1,%2,%3}, {%4,%5,%6,%7}, {%8,%9}, {%0,%1,%2,%3};"
        : "+f"(c[0]), "+f"(c[1]), "+f"(c[2]), "+f"(c[3])
        : "r"(a0), "r"(a1), "r"(a2), "r"(a3), "r"(b0), "r"(b1));
}
static __device__ __forceinline__ uint32_t lds32(const char* p) {
    return *(const uint32_t*)p;
}

// one encoding task: pixel p (global pid), level lv -> A1 hi/lo fp16 (scaled)
static __device__ __forceinline__ void enc_one(const float* __restrict__ tab,
                                               char* sm, int pid, int lv, int p)
{
    const float    sc  = c_scale[lv];
    const unsigned res = c_res[lv];
    const float cx = (float)(pid & 1023) * (1.0f / 1023.0f);
    const float cy = (float)(pid >> 10)  * (1.0f / 1023.0f);

    float posx = fmaf(cx, sc, 0.5f);
    float fx = floorf(posx); float wx = posx - fx;
    float posy = fmaf(cy, sc, 0.5f);
    float fy = floorf(posy); float wy = posy - fy;
    unsigned px0 = (unsigned)fx, py0 = (unsigned)fy;
    unsigned px1 = min(px0 + 1u, res - 1u);
    unsigned py1 = min(py0 + 1u, res - 1u);

    unsigned i00, i10, i01, i11;
    if (lv < 11) {
        i00 = px0 + py0 * res; i10 = px1 + py0 * res;
        i01 = px0 + py1 * res; i11 = px1 + py1 * res;
    } else {
        unsigned hy0 = py0 * 2654435761u, hy1 = py1 * 2654435761u;
        i00 = (px0 ^ hy0) & T_MASK; i10 = (px1 ^ hy0) & T_MASK;
        i01 = (px0 ^ hy1) & T_MASK; i11 = (px1 ^ hy1) & T_MASK;
    }

    const float4* tb = (const float4*)tab + ((size_t)lv << 20);
    float4 v00 = __ldg(tb + i00);
    float4 v10 = __ldg(tb + i10);
    float4 v01 = __ldg(tb + i01);
    float4 v11 = __ldg(tb + i11);

    // bilinear weights scaled by ENC_SCALE (exact power of two)
    float ux = (1.0f - wx) * ENC_SCALE, sxw = wx * ENC_SCALE;
    float w00 = ux * (1.0f - wy);
    float w10 = sxw * (1.0f - wy);
    float w01 = ux * wy;
    float w11 = sxw * wy;

    float f0 = v00.x * w00 + v10.x * w10 + v01.x * w01 + v11.x * w11;
    float f1 = v00.y * w00 + v10.y * w10 + v01.y * w01 + v11.y * w11;
    float f2 = v00.z * w00 + v10.z * w10 + v01.z * w01 + v11.z * w11;
    float f3 = v00.w * w00 + v10.w * w10 + v01.w * w01 + v11.w * w11;

    // fp16 hi/lo split
    float h0 = __half2float(__float2half_rn(f0)), l0 = f0 - h0;
    float h1 = __half2float(__float2half_rn(f1)), l1 = f1 - h1;
    float h2 = __half2float(__float2half_rn(f2)), l2 = f2 - h2;
    float h3 = __half2float(__float2half_rn(f3)), l3 = f3 - h3;

    uint32_t off = (uint32_t)(p * P1 + lv * 8);   // 4 fp16 = 8 B
    *(uint2*)(sm + SO_A1HI + off) = make_uint2(pk(h0, h1), pk(h2, h3));
    *(uint2*)(sm + SO_A1LO + off) = make_uint2(pk(l0, l1), pk(l2, l3));
}

// ---- prep: pack transposed weights into fragment uint2 layout ----
__global__ void prep_kernel(const float* __restrict__ w1,
                            const float* __restrict__ w2) {
    int i = blockIdx.x * blockDim.x + threadIdx.x;
    if (i == 0) g_ctr = 0u;
    if (i < 3 * 4 * 132) {
        int n = i % 132, r = i / 132;
        int qc = r & 3, s = r >> 2;
        uint2 v = make_uint2(0u, 0u);
        if (n < 128) {
            int k0 = s * 16 + qc * 2;
            __half2 a = __floats2half2_rn(w1[k0 * 128 + n], w1[(k0 + 1) * 128 + n]);
            __half2 b = __floats2half2_rn(w1[(k0 + 8) * 128 + n], w1[(k0 + 9) * 128 + n]);
            v.x = *(uint32_t*)&a;
            v.y = *(uint32_t*)&b;
        }
        g_b1p[i] = v;
    }
    if (i < 8 * 4 * 132) {
        int n = i % 132, r = i / 132;
        int qc = r & 3, s = r >> 2;
        uint2 v = make_uint2(0u, 0u);
        if (n < 128) {
            int k0 = s * 16 + qc * 2;
            __half2 a = __floats2half2_rn(w2[k0 * 128 + n], w2[(k0 + 1) * 128 + n]);
            __half2 b = __floats2half2_rn(w2[(k0 + 8) * 128 + n], w2[(k0 + 9) * 128 + n]);
            v.x = *(uint32_t*)&a;
            v.y = *(uint32_t*)&b;
        }
        g_b2p[i] = v;
    }
}

extern "C" __global__ void __launch_bounds__(THREADS, 2)
inr_mma_kernel(const float* __restrict__ tab,
               const float* __restrict__ w3g,
               float* __restrict__ out,
               int NT)
{
    extern __shared__ char sm[];
    __shared__ unsigned sh_tile;
    const uint32_t sb = smem_u32(sm);
    const int t  = threadIdx.x;
    const int w  = t >> 5;
    const int ln = t & 31;
    const int qr = ln >> 2;
    const int qc = ln & 3;
    const int wm = w & 1;
    const int wn = w >> 1;
    const int p  = t & 127;
    const int lvh = t >> 7;

    // ---- stage packed weights once per persistent CTA ----
    for (int i = t; i < 792; i += THREADS)
        cp16(sb + SO_B1 + i * 16, (const char*)g_b1p + i * 16);
    for (int i = t; i < 2112; i += THREADS)
        cp16(sb + SO_B2 + i * 16, (const char*)g_b2p + i * 16);
    if (t < 32) cp16(sb + SO_W3 + t * 16, w3g + t * 4);
    asm volatile("cp.async.commit_group;\n" ::: "memory");

    if (t == 0) sh_tile = atomicAdd(&g_ctr, 1u);
    asm volatile("cp.async.wait_group 0;\n" ::: "memory");
    __syncthreads();
    unsigned cur = sh_tile;

    float acc[4][4][4];

    while (cur < (unsigned)NT) {
        // ---- encoding: 128 px x 12 levels (6 tasks/thread) ----
        #pragma unroll
        for (int it = 0; it < 6; it++)
            enc_one(tab, sm, (int)cur * PIX + p, it * 2 + lvh, p);
        __syncthreads();

        // ====== GEMM1: K=48, A split fp16 (2 terms), B single fp16 ======
        #pragma unroll
        for (int i = 0; i < 4; i++)
            #pragma unroll
            for (int j = 0; j < 4; j++)
                #pragma unroll
                for (int q = 0; q < 4; q++) acc[i][j][q] = 0.0f;

        {
            const char* aH = sm + SO_A1HI + (wm * 64 + qr) * P1 + qc * 4;
            const char* aL = sm + SO_A1LO + (wm * 64 + qr) * P1 + qc * 4;

            #pragma unroll
            for (int s = 0; s < 3; s++) {
                const int ko = s * 32;
                uint32_t Ah[4][4], Al[4][4];
                #pragma unroll
                for (int mf = 0; mf < 4; mf++) {
                    const int ro = mf * 16 * P1 + ko;
                    Ah[mf][0] = lds32(aH + ro);
                    Ah[mf][1] = lds32(aH + ro + 8 * P1);
                    Ah[mf][2] = lds32(aH + ro + 16);
                    Ah[mf][3] = lds32(aH + ro + 8 * P1 + 16);
                    Al[mf][0] = lds32(aL + ro);
                    Al[mf][1] = lds32(aL + ro + 8 * P1);
                    Al[mf][2] = lds32(aL + ro + 16);
                    Al[mf][3] = lds32(aL + ro + 8 * P1 + 16);
                }
                uint2 B[4];
                #pragma unroll
                for (int nf = 0; nf < 4; nf++)
                    B[nf] = *(const uint2*)(sm + B1OFF(s, qc, wn * 32 + nf * 8 + qr));
                #pragma unroll
                for (int mf = 0; mf < 4; mf++)
                    #pragma unroll
                    for (int nf = 0; nf < 4; nf++) {
                        float* c = acc[mf][nf];
                        mmah(c, Ah[mf][0], Ah[mf][1], Ah[mf][2], Ah[mf][3],
                             B[nf].x, B[nf].y);
                        mmah(c, Al[mf][0], Al[mf][1], Al[mf][2], Al[mf][3],
                             B[nf].x, B[nf].y);
                    }
            }
        }

        // ---- epilogue1: relu -> fp16 -> fragment-major uint4 A2 ----
        {
            const int rg = (wm * 4 + 0) * 8 + qr;   // + mf*8 added in loop
            #pragma unroll
            for (int mf = 0; mf < 4; mf++) {
                #pragma unroll
                for (int j = 0; j < 2; j++) {
                    const int nfA = 2 * j, nfB = 2 * j + 1;
                    uint4 v;
                    v.x = pk(fmaxf(acc[mf][nfA][0], 0.0f),
                             fmaxf(acc[mf][nfA][1], 0.0f));
                    v.y = pk(fmaxf(acc[mf][nfA][2], 0.0f),
                             fmaxf(acc[mf][nfA][3], 0.0f));
                    v.z = pk(fmaxf(acc[mf][nfB][0], 0.0f),
                             fmaxf(acc[mf][nfB][1], 0.0f));
                    v.w = pk(fmaxf(acc[mf][nfB][2], 0.0f),
                             fmaxf(acc[mf][nfB][3], 0.0f));
                    *(uint4*)(sm + A2FOFF(2 * wn + j, qc, rg + mf * 8)) = v;
                }
            }
        }
        if (t == 0) sh_tile = atomicAdd(&g_ctr, 1u);
        __syncthreads();

        // ====== GEMM2: K=128, single fp16 x single fp16 ======
        #pragma unroll
        for (int i = 0; i < 4; i++)
            #pragma unroll
            for (int j = 0; j < 4; j++)
                #pragma unroll
                for (int q = 0; q < 4; q++) acc[i][j][q] = 0.0f;

        {
            #pragma unroll
            for (int s = 0; s < 8; s++) {
                uint4 A[4];
                #pragma unroll
                for (int mf = 0; mf < 4; mf++)
                    A[mf] = *(const uint4*)(sm + A2FOFF(s, qc, (wm * 4 + mf) * 8 + qr));
                uint2 B[4];
                #pragma unroll
                for (int nf = 0; nf < 4; nf++)
                    B[nf] = *(const uint2*)(sm + B2OFF(s, qc, wn * 32 + nf * 8 + qr));
                #pragma unroll
                for (int mf = 0; mf < 4; mf++)
                    #pragma unroll
                    for (int nf = 0; nf < 4; nf++)
                        mmah(acc[mf][nf], A[mf].x, A[mf].y, A[mf].z, A[mf].w,
                             B[nf].x, B[nf].y);
            }
        }

        // ---- epilogue2: dot w3, quad-reduce -> PARTS ----
        {
            const float* w3s = (const float*)(sm + SO_W3);
            float* parts = (float*)(sm + SO_PARTS);
            const int colb = wn * 32 + qc * 2;
            #pragma unroll
            for (int mf = 0; mf < 4; mf++) {
                float p0 = 0.0f, p1 = 0.0f;
                #pragma unroll
                for (int nf = 0; nf < 4; nf++) {
                    const int col = colb + nf * 8;
                    float wa = w3s[col], wb = w3s[col + 1];
                    p0 += fmaxf(acc[mf][nf][0], 0.0f) * wa
                        + fmaxf(acc[mf][nf][1], 0.0f) * wb;
                    p1 += fmaxf(acc[mf][nf][2], 0.0f) * wa
                        + fmaxf(acc[mf][nf][3], 0.0f) * wb;
                }
                p0 += __shfl_xor_sync(0xffffffffu, p0, 1);
                p0 += __shfl_xor_sync(0xffffffffu, p0, 2);
                p1 += __shfl_xor_sync(0xffffffffu, p1, 1);
                p1 += __shfl_xor_sync(0xffffffffu, p1, 2);
                if (qc == 0) {
                    const int r0 = wm * 64 + mf * 16 + qr;
                    parts[r0 * 4 + wn]       = p0;
                    parts[(r0 + 8) * 4 + wn] = p1;
                }
            }
        }
        __syncthreads();

        if (t < PIX) {
            const float* q = (const float*)(sm + SO_PARTS) + t * 4;
            out[cur * PIX + t] = ((q[0] + q[1]) + (q[2] + q[3])) * OUT_SCALE;
        }

        const unsigned nxt = sh_tile;
        __syncthreads();     // out read of PARTS done; A1 free for next enc
        cur = nxt;
    }
}

extern "C" void kernel_launch(void* const* d_in, const int* in_sizes, int n_in,
                              void* d_out, int out_size)
{
    // inputs: [0]=H, [1]=W, [2]=table f32[12*2^20*4],
    //         [3]=w1 f32[48*128], [4]=w2 f32[128*128], [5]=w3 f32[128]
    const float* tab = (const float*)d_in[2];
    const float* w1  = (const float*)d_in[3];
    const float* w2  = (const float*)d_in[4];
    const float* w3  = (const float*)d_in[5];
    float* out = (float*)d_out;

    cudaFuncSetAttribute(inr_mma_kernel,
                         cudaFuncAttributeMaxDynamicSharedMemorySize, SMEM_BYTES);

    prep_kernel<<<17, 256>>>(w1, w2);      // packs weights, resets g_ctr
    const int NT = out_size / PIX;         // 8192 tiles
    inr_mma_kernel<<<304, THREADS, SMEM_BYTES>>>(tab, w3, out, NT);
}

// round 12
// speedup vs baseline: 12.3300x; 1.1994x over previous
#include <cuda_runtime.h>
#include <cuda_fp16.h>
#include <cstdint>

// TCNN_INR fused, R7: fp16 tensor-core MLP, fragment-major everywhere.
//   - Activation scaling 2^12 (net positively homogeneous), descale at out.
//   - GEMM1: single fp16 x single fp16 (A-split dropped; error budget holds:
//     4 independent 2^-12 RN sources -> ~3-4e-4 vs 1e-3 gate).
//   - A1 written FRAGMENT-MAJOR by the encoder (2 STS.32/task), so both
//     GEMMs load A as 4x LDS.128 per kstep, conflict-free.
//   - 176 HMMA/warp/tile. smem 93KB -> 2 CTAs/SM, grid 304 persistent.

#define THREADS 256
#define PIX     128
#define T_MASK  ((1u << 20) - 1u)
#define ENC_SCALE   4096.0f
#define OUT_SCALE   (1.0f / 4096.0f)

__constant__ float c_scale[12] = {
    15.0f, 23.0f, 35.0f, 53.0f, 80.0f, 120.5f, 181.25f, 272.375f,
    409.0625f, 614.09375f, 921.640625f, 1382.9609375f};
__constant__ unsigned c_res[12] = {
    16u, 24u, 36u, 54u, 81u, 122u, 183u, 274u, 411u, 616u, 923u, 1384u};

// prep output: fragment-packed transposed weights (uint2 = {b0,b1} frags)
__device__ __align__(16) uint2 g_b1p[3 * 4 * 132];    // [s][qc][n pad 132]
__device__ __align__(16) uint2 g_b2p[8 * 4 * 132];
__device__ unsigned g_ctr;

// ---- smem byte offsets ----
#define SO_W3    0                  // 512
#define SO_PARTS 512                // 2048
#define SO_A1F   2560               // 3*4*66*16 = 12672
#define SO_B1    15232              // 12672
#define SO_B2    27904              // 8*4*132*8 = 33792
#define SO_A2F   61696              // 8*4*66*16 = 33792
#define SMEM_BYTES 95488

#define B1OFF(s,qc,n)   (SO_B1  + ((((s)<<2)+(qc))*132 + (n))*8)
#define B2OFF(s,qc,n)   (SO_B2  + ((((s)<<2)+(qc))*132 + (n))*8)
#define A1FOFF(s,qc,rg) (SO_A1F + ((((s)<<2)+(qc))*66 + (rg))*16)
#define A2FOFF(s,qc,rg) (SO_A2F + ((((s)<<2)+(qc))*66 + (rg))*16)

static __device__ __forceinline__ void cp16(uint32_t dst, const void* src) {
    asm volatile("cp.async.cg.shared.global [%0], [%1], 16;\n" :: "r"(dst), "l"(src));
}
static __device__ __forceinline__ uint32_t smem_u32(const void* p) {
    uint32_t a;
    asm("{ .reg .u64 t; cvta.to.shared.u64 t, %1; cvt.u32.u64 %0, t; }"
        : "=r"(a) : "l"(p));
    return a;
}
static __device__ __forceinline__ uint32_t pk(float lo, float hi) {
    uint32_t r;
    asm("cvt.rn.f16x2.f32 %0, %1, %2;" : "=r"(r) : "f"(hi), "f"(lo));
    return r;
}
static __device__ __forceinline__ void mmah(float* c,
        uint32_t a0, uint32_t a1, uint32_t a2, uint32_t a3,
        uint32_t b0, uint32_t b1) {
    asm volatile(
        "mma.sync.aligned.m16n8k16.row.col.f32.f16.f16.f32 "
        "{%0,%1,%2,%3}, {%4,%5,%6,%7}, {%8,%9}, {%0,%1,%2,%3};"
        : "+f"(c[0]), "+f"(c[1]), "+f"(c[2]), "+f"(c[3])
        : "r"(a0), "r"(a1), "r"(a2), "r"(a3), "r"(b0), "r"(b1));
}

// one encoding task: pixel p (global pid), level lv -> 2 f16x2 words into
// the fragment-major A1 structure.
//   k0 = 4*lv; kstep s = lv>>2; quad-col qc = 2*(lv&1) (word1 at qc+1);
//   khigh = (lv>>1)&1; slot = upper + 2*khigh, upper = (p>>3)&1;
//   rowgroup rg = (p>>4)*8 + (p&7).
static __device__ __forceinline__ void enc_one(const float* __restrict__ tab,
                                               char* sm, int pid, int lv, int p)
{
    const float    sc  = c_scale[lv];
    const unsigned res = c_res[lv];
    const float cx = (float)(pid & 1023) * (1.0f / 1023.0f);
    const float cy = (float)(pid >> 10)  * (1.0f / 1023.0f);

    float posx = fmaf(cx, sc, 0.5f);
    float fx = floorf(posx); float wx = posx - fx;
    float posy = fmaf(cy, sc, 0.5f);
    float fy = floorf(posy); float wy = posy - fy;
    unsigned px0 = (unsigned)fx, py0 = (unsigned)fy;
    unsigned px1 = min(px0 + 1u, res - 1u);
    unsigned py1 = min(py0 + 1u, res - 1u);

    unsigned i00, i10, i01, i11;
    if (lv < 11) {
        i00 = px0 + py0 * res; i10 = px1 + py0 * res;
        i01 = px0 + py1 * res; i11 = px1 + py1 * res;
    } else {
        unsigned hy0 = py0 * 2654435761u, hy1 = py1 * 2654435761u;
        i00 = (px0 ^ hy0) & T_MASK; i10 = (px1 ^ hy0) & T_MASK;
        i01 = (px0 ^ hy1) & T_MASK; i11 = (px1 ^ hy1) & T_MASK;
    }

    const float4* tb = (const float4*)tab + ((size_t)lv << 20);
    float4 v00 = __ldg(tb + i00);
    float4 v10 = __ldg(tb + i10);
    float4 v01 = __ldg(tb + i01);
    float4 v11 = __ldg(tb + i11);

    float ux = (1.0f - wx) * ENC_SCALE, sxw = wx * ENC_SCALE;
    float w00 = ux * (1.0f - wy);
    float w10 = sxw * (1.0f - wy);
    float w01 = ux * wy;
    float w11 = sxw * wy;

    float f0 = v00.x * w00 + v10.x * w10 + v01.x * w01 + v11.x * w11;
    float f1 = v00.y * w00 + v10.y * w10 + v01.y * w01 + v11.y * w11;
    float f2 = v00.z * w00 + v10.z * w10 + v01.z * w01 + v11.z * w11;
    float f3 = v00.w * w00 + v10.w * w10 + v01.w * w01 + v11.w * w11;

    const int s     = lv >> 2;
    const int qc    = (lv & 1) * 2;
    const int slot  = ((p >> 3) & 1) + ((lv >> 1) & 1) * 2;
    const int rg    = (p >> 4) * 8 + (p & 7);

    *(uint32_t*)(sm + A1FOFF(s, qc,     rg) + slot * 4) = pk(f0, f1);
    *(uint32_t*)(sm + A1FOFF(s, qc + 1, rg) + slot * 4) = pk(f2, f3);
}

// ---- prep: pack transposed weights into fragment uint2 layout ----
__global__ void prep_kernel(const float* __restrict__ w1,
                            const float* __restrict__ w2) {
    int i = blockIdx.x * blockDim.x + threadIdx.x;
    if (i == 0) g_ctr = 0u;
    if (i < 3 * 4 * 132) {
        int n = i % 132, r = i / 132;
        int qc = r & 3, s = r >> 2;
        uint2 v = make_uint2(0u, 0u);
        if (n < 128) {
            int k0 = s * 16 + qc * 2;
            __half2 a = __floats2half2_rn(w1[k0 * 128 + n], w1[(k0 + 1) * 128 + n]);
            __half2 b = __floats2half2_rn(w1[(k0 + 8) * 128 + n], w1[(k0 + 9) * 128 + n]);
            v.x = *(uint32_t*)&a;
            v.y = *(uint32_t*)&b;
        }
        g_b1p[i] = v;
    }
    if (i < 8 * 4 * 132) {
        int n = i % 132, r = i / 132;
        int qc = r & 3, s = r >> 2;
        uint2 v = make_uint2(0u, 0u);
        if (n < 128) {
            int k0 = s * 16 + qc * 2;
            __half2 a = __floats2half2_rn(w2[k0 * 128 + n], w2[(k0 + 1) * 128 + n]);
            __half2 b = __floats2half2_rn(w2[(k0 + 8) * 128 + n], w2[(k0 + 9) * 128 + n]);
            v.x = *(uint32_t*)&a;
            v.y = *(uint32_t*)&b;
        }
        g_b2p[i] = v;
    }
}

extern "C" __global__ void __launch_bounds__(THREADS, 2)
inr_mma_kernel(const float* __restrict__ tab,
               const float* __restrict__ w3g,
               float* __restrict__ out,
               int NT)
{
    extern __shared__ char sm[];
    __shared__ unsigned sh_tile;
    const uint32_t sb = smem_u32(sm);
    const int t  = threadIdx.x;
    const int w  = t >> 5;
    const int ln = t & 31;
    const int qr = ln >> 2;
    const int qc = ln & 3;
    const int wm = w & 1;
    const int wn = w >> 1;
    const int p  = t & 127;
    const int lvh = t >> 7;

    // ---- stage packed weights once per persistent CTA ----
    for (int i = t; i < 792; i += THREADS)
        cp16(sb + SO_B1 + i * 16, (const char*)g_b1p + i * 16);
    for (int i = t; i < 2112; i += THREADS)
        cp16(sb + SO_B2 + i * 16, (const char*)g_b2p + i * 16);
    if (t < 32) cp16(sb + SO_W3 + t * 16, w3g + t * 4);
    asm volatile("cp.async.commit_group;\n" ::: "memory");

    if (t == 0) sh_tile = atomicAdd(&g_ctr, 1u);
    asm volatile("cp.async.wait_group 0;\n" ::: "memory");
    __syncthreads();
    unsigned cur = sh_tile;

    float acc[4][4][4];

    while (cur < (unsigned)NT) {
        // ---- encoding: 128 px x 12 levels (6 tasks/thread) ----
        #pragma unroll
        for (int it = 0; it < 6; it++)
            enc_one(tab, (char*)sm, (int)cur * PIX + p, it * 2 + lvh, p);
        __syncthreads();

        // ====== GEMM1: K=48, single fp16 x single fp16 ======
        #pragma unroll
        for (int i = 0; i < 4; i++)
            #pragma unroll
            for (int j = 0; j < 4; j++)
                #pragma unroll
                for (int q = 0; q < 4; q++) acc[i][j][q] = 0.0f;

        {
            #pragma unroll
            for (int s = 0; s < 3; s++) {
                uint4 A[4];
                #pragma unroll
                for (int mf = 0; mf < 4; mf++)
                    A[mf] = *(const uint4*)(sm + A1FOFF(s, qc, (wm * 4 + mf) * 8 + qr));
                uint2 B[4];
                #pragma unroll
                for (int nf = 0; nf < 4; nf++)
                    B[nf] = *(const uint2*)(sm + B1OFF(s, qc, wn * 32 + nf * 8 + qr));
                #pragma unroll
                for (int mf = 0; mf < 4; mf++)
                    #pragma unroll
                    for (int nf = 0; nf < 4; nf++)
                        mmah(acc[mf][nf], A[mf].x, A[mf].y, A[mf].z, A[mf].w,
                             B[nf].x, B[nf].y);
            }
        }

        // ---- epilogue1: relu -> fp16 -> fragment-major uint4 A2 ----
        {
            const int rg = wm * 32 + qr;     // + mf*8 added in loop
            #pragma unroll
            for (int mf = 0; mf < 4; mf++) {
                #pragma unroll
                for (int j = 0; j < 2; j++) {
                    const int nfA = 2 * j, nfB = 2 * j + 1;
                    uint4 v;
                    v.x = pk(fmaxf(acc[mf][nfA][0], 0.0f),
                             fmaxf(acc[mf][nfA][1], 0.0f));
                    v.y = pk(fmaxf(acc[mf][nfA][2], 0.0f),
                             fmaxf(acc[mf][nfA][3], 0.0f));
                    v.z = pk(fmaxf(acc[mf][nfB][0], 0.0f),
                             fmaxf(acc[mf][nfB][1], 0.0f));
                    v.w = pk(fmaxf(acc[mf][nfB][2], 0.0f),
                             fmaxf(acc[mf][nfB][3], 0.0f));
                    *(uint4*)(sm + A2FOFF(2 * wn + j, qc, rg + mf * 8)) = v;
                }
            }
        }
        if (t == 0) sh_tile = atomicAdd(&g_ctr, 1u);
        __syncthreads();

        // ====== GEMM2: K=128, single fp16 x single fp16 ======
        #pragma unroll
        for (int i = 0; i < 4; i++)
            #pragma unroll
            for (int j = 0; j < 4; j++)
                #pragma unroll
                for (int q = 0; q < 4; q++) acc[i][j][q] = 0.0f;

        {
            #pragma unroll
            for (int s = 0; s < 8; s++) {
                uint4 A[4];
                #pragma unroll
                for (int mf = 0; mf < 4; mf++)
                    A[mf] = *(const uint4*)(sm + A2FOFF(s, qc, (wm * 4 + mf) * 8 + qr));
                uint2 B[4];
                #pragma unroll
                for (int nf = 0; nf < 4; nf++)
                    B[nf] = *(const uint2*)(sm + B2OFF(s, qc, wn * 32 + nf * 8 + qr));
                #pragma unroll
                for (int mf = 0; mf < 4; mf++)
                    #pragma unroll
                    for (int nf = 0; nf < 4; nf++)
                        mmah(acc[mf][nf], A[mf].x, A[mf].y, A[mf].z, A[mf].w,
                             B[nf].x, B[nf].y);
            }
        }

        // ---- epilogue2: dot w3, quad-reduce -> PARTS ----
        {
            const float* w3s = (const float*)(sm + SO_W3);
            float* parts = (float*)(sm + SO_PARTS);
            const int colb = wn * 32 + qc * 2;
            #pragma unroll
            for (int mf = 0; mf < 4; mf++) {
                float p0 = 0.0f, p1 = 0.0f;
                #pragma unroll
                for (int nf = 0; nf < 4; nf++) {
                    const int col = colb + nf * 8;
                    float wa = w3s[col], wb = w3s[col + 1];
                    p0 += fmaxf(acc[mf][nf][0], 0.0f) * wa
                        + fmaxf(acc[mf][nf][1], 0.0f) * wb;
                    p1 += fmaxf(acc[mf][nf][2], 0.0f) * wa
                        + fmaxf(acc[mf][nf][3], 0.0f) * wb;
                }
                p0 += __shfl_xor_sync(0xffffffffu, p0, 1);
                p0 += __shfl_xor_sync(0xffffffffu, p0, 2);
                p1 += __shfl_xor_sync(0xffffffffu, p1, 1);
                p1 += __shfl_xor_sync(0xffffffffu, p1, 2);
                if (qc == 0) {
                    const int r0 = wm * 64 + mf * 16 + qr;
                    parts[r0 * 4 + wn]       = p0;
                    parts[(r0 + 8) * 4 + wn] = p1;
                }
            }
        }
        __syncthreads();

        if (t < PIX) {
            const float* q = (const float*)(sm + SO_PARTS) + t * 4;
            out[cur * PIX + t] = ((q[0] + q[1]) + (q[2] + q[3])) * OUT_SCALE;
        }

        const unsigned nxt = sh_tile;
        __syncthreads();     // PARTS read done; A1F free for next encoding
        cur = nxt;
    }
}

extern "C" void kernel_launch(void* const* d_in, const int* in_sizes, int n_in,
                              void* d_out, int out_size)
{
    // inputs: [0]=H, [1]=W, [2]=table f32[12*2^20*4],
    //         [3]=w1 f32[48*128], [4]=w2 f32[128*128], [5]=w3 f32[128]
    const float* tab = (const float*)d_in[2];
    const float* w1  = (const float*)d_in[3];
    const float* w2  = (const float*)d_in[4];
    const float* w3  = (const float*)d_in[5];
    float* out = (float*)d_out;

    cudaFuncSetAttribute(inr_mma_kernel,
                         cudaFuncAttributeMaxDynamicSharedMemorySize, SMEM_BYTES);

    prep_kernel<<<17, 256>>>(w1, w2);      // packs weights, resets g_ctr
    const int NT = out_size / PIX;         // 8192 tiles
    inr_mma_kernel<<<304, THREADS, SMEM_BYTES>>>(tab, w3, out, NT);
}

// round 16
// speedup vs baseline: 12.4080x; 1.0063x over previous
#include <cuda_runtime.h>
#include <cuda_fp16.h>
#include <cstdint>

// TCNN_INR fused, R8: 64x64 warp tiles to cut smem fragment redundancy.
//   - CTA = 128 threads (4 warps), each warp owns 64 rows x 64 cols:
//     A read 2x, B read 2x (vs 4x/2x with 64x32) -> GEMM smem wf -33%.
//   - 2 CTAs/SM (regs: 128 acc + operands fits in 256/thread budget).
//   - Same fp16 single-single MMA + 2^12 activation scaling as R7.
//   - Encoding: 12 tasks/thread (128 px x 12 levels / 128 threads).

#define THREADS 128
#define PIX     128
#define T_MASK  ((1u << 20) - 1u)
#define ENC_SCALE   4096.0f
#define OUT_SCALE   (1.0f / 4096.0f)

__constant__ float c_scale[12] = {
    15.0f, 23.0f, 35.0f, 53.0f, 80.0f, 120.5f, 181.25f, 272.375f,
    409.0625f, 614.09375f, 921.640625f, 1382.9609375f};
__constant__ unsigned c_res[12] = {
    16u, 24u, 36u, 54u, 81u, 122u, 183u, 274u, 411u, 616u, 923u, 1384u};

// prep output: fragment-packed transposed weights (uint2 = {b0,b1} frags)
__device__ __align__(16) uint2 g_b1p[3 * 4 * 132];    // [s][qc][n pad 132]
__device__ __align__(16) uint2 g_b2p[8 * 4 * 132];
__device__ unsigned g_ctr;

// ---- smem byte offsets ----
#define SO_W3    0                  // 512
#define SO_PARTS 512                // 128*2*4 = 1024
#define SO_A1F   2560               // 3*4*66*16 = 12672
#define SO_B1    15232              // 12672
#define SO_B2    27904              // 8*4*132*8 = 33792
#define SO_A2F   61696              // 33792
#define SMEM_BYTES 95488

#define B1OFF(s,qc,n)   (SO_B1  + ((((s)<<2)+(qc))*132 + (n))*8)
#define B2OFF(s,qc,n)   (SO_B2  + ((((s)<<2)+(qc))*132 + (n))*8)
#define A1FOFF(s,qc,rg) (SO_A1F + ((((s)<<2)+(qc))*66 + (rg))*16)
#define A2FOFF(s,qc,rg) (SO_A2F + ((((s)<<2)+(qc))*66 + (rg))*16)

static __device__ __forceinline__ void cp16(uint32_t dst, const void* src) {
    asm volatile("cp.async.cg.shared.global [%0], [%1], 16;\n" :: "r"(dst), "l"(src));
}
static __device__ __forceinline__ uint32_t smem_u32(const void* p) {
    uint32_t a;
    asm("{ .reg .u64 t; cvta.to.shared.u64 t, %1; cvt.u32.u64 %0, t; }"
        : "=r"(a) : "l"(p));
    return a;
}
static __device__ __forceinline__ uint32_t pk(float lo, float hi) {
    uint32_t r;
    asm("cvt.rn.f16x2.f32 %0, %1, %2;" : "=r"(r) : "f"(hi), "f"(lo));
    return r;
}
static __device__ __forceinline__ void mmah(float* c,
        uint32_t a0, uint32_t a1, uint32_t a2, uint32_t a3,
        uint32_t b0, uint32_t b1) {
    asm volatile(
        "mma.sync.aligned.m16n8k16.row.col.f32.f16.f16.f32 "
        "{%0,%1,%2,%3}, {%4,%5,%6,%7}, {%8,%9}, {%0,%1,%2,%3};"
        : "+f"(c[0]), "+f"(c[1]), "+f"(c[2]), "+f"(c[3])
        : "r"(a0), "r"(a1), "r"(a2), "r"(a3), "r"(b0), "r"(b1));
}

// one encoding task: pixel p (global pid), level lv -> 2 f16x2 words into
// fragment-major A1 (s = lv>>2, qc = 2*(lv&1) (+1), slot = (p>>3)&1 +
// 2*((lv>>1)&1), rg = (p>>4)*8 + (p&7)).
static __device__ __forceinline__ void enc_one(const float* __restrict__ tab,
                                               char* sm, int pid, int lv, int p)
{
    const float    sc  = c_scale[lv];
    const unsigned res = c_res[lv];
    const float cx = (float)(pid & 1023) * (1.0f / 1023.0f);
    const float cy = (float)(pid >> 10)  * (1.0f / 1023.0f);

    float posx = fmaf(cx, sc, 0.5f);
    float fx = floorf(posx); float wx = posx - fx;
    float posy = fmaf(cy, sc, 0.5f);
    float fy = floorf(posy); float wy = posy - fy;
    unsigned px0 = (unsigned)fx, py0 = (unsigned)fy;
    unsigned px1 = min(px0 + 1u, res - 1u);
    unsigned py1 = min(py0 + 1u, res - 1u);

    unsigned i00, i10, i01, i11;
    if (lv < 11) {
        i00 = px0 + py0 * res; i10 = px1 + py0 * res;
        i01 = px0 + py1 * res; i11 = px1 + py1 * res;
    } else {
        unsigned hy0 = py0 * 2654435761u, hy1 = py1 * 2654435761u;
        i00 = (px0 ^ hy0) & T_MASK; i10 = (px1 ^ hy0) & T_MASK;
        i01 = (px0 ^ hy1) & T_MASK; i11 = (px1 ^ hy1) & T_MASK;
    }

    const float4* tb = (const float4*)tab + ((size_t)lv << 20);
    float4 v00 = __ldg(tb + i00);
    float4 v10 = __ldg(tb + i10);
    float4 v01 = __ldg(tb + i01);
    float4 v11 = __ldg(tb + i11);

    float ux = (1.0f - wx) * ENC_SCALE, sxw = wx * ENC_SCALE;
    float w00 = ux * (1.0f - wy);
    float w10 = sxw * (1.0f - wy);
    float w01 = ux * wy;
    float w11 = sxw * wy;

    float f0 = v00.x * w00 + v10.x * w10 + v01.x * w01 + v11.x * w11;
    float f1 = v00.y * w00 + v10.y * w10 + v01.y * w01 + v11.y * w11;
    float f2 = v00.z * w00 + v10.z * w10 + v01.z * w01 + v11.z * w11;
    float f3 = v00.w * w00 + v10.w * w10 + v01.w * w01 + v11.w * w11;

    const int s     = lv >> 2;
    const int qcb   = (lv & 1) * 2;
    const int slot  = ((p >> 3) & 1) + ((lv >> 1) & 1) * 2;
    const int rg    = (p >> 4) * 8 + (p & 7);

    *(uint32_t*)(sm + A1FOFF(s, qcb,     rg) + slot * 4) = pk(f0, f1);
    *(uint32_t*)(sm + A1FOFF(s, qcb + 1, rg) + slot * 4) = pk(f2, f3);
}

// ---- prep: pack transposed weights into fragment uint2 layout ----
__global__ void prep_kernel(const float* __restrict__ w1,
                            const float* __restrict__ w2) {
    int i = blockIdx.x * blockDim.x + threadIdx.x;
    if (i == 0) g_ctr = 0u;
    if (i < 3 * 4 * 132) {
        int n = i % 132, r = i / 132;
        int qc = r & 3, s = r >> 2;
        uint2 v = make_uint2(0u, 0u);
        if (n < 128) {
            int k0 = s * 16 + qc * 2;
            __half2 a = __floats2half2_rn(w1[k0 * 128 + n], w1[(k0 + 1) * 128 + n]);
            __half2 b = __floats2half2_rn(w1[(k0 + 8) * 128 + n], w1[(k0 + 9) * 128 + n]);
            v.x = *(uint32_t*)&a;
            v.y = *(uint32_t*)&b;
        }
        g_b1p[i] = v;
    }
    if (i < 8 * 4 * 132) {
        int n = i % 132, r = i / 132;
        int qc = r & 3, s = r >> 2;
        uint2 v = make_uint2(0u, 0u);
        if (n < 128) {
            int k0 = s * 16 + qc * 2;
            __half2 a = __floats2half2_rn(w2[k0 * 128 + n], w2[(k0 + 1) * 128 + n]);
            __half2 b = __floats2half2_rn(w2[(k0 + 8) * 128 + n], w2[(k0 + 9) * 128 + n]);
            v.x = *(uint32_t*)&a;
            v.y = *(uint32_t*)&b;
        }
        g_b2p[i] = v;
    }
}

extern "C" __global__ void __launch_bounds__(THREADS, 2)
inr_mma_kernel(const float* __restrict__ tab,
               const float* __restrict__ w3g,
               float* __restrict__ out,
               int NT)
{
    extern __shared__ char sm[];
    __shared__ unsigned sh_tile;
    const uint32_t sb = smem_u32(sm);
    const int t  = threadIdx.x;
    const int w  = t >> 5;          // 4 warps
    const int ln = t & 31;
    const int qr = ln >> 2;
    const int qc = ln & 3;
    const int wm = w & 1;           // M half (64 rows)
    const int wn = w >> 1;          // N half (64 cols)

    // ---- stage packed weights once per persistent CTA ----
    for (int i = t; i < 792; i += THREADS)
        cp16(sb + SO_B1 + i * 16, (const char*)g_b1p + i * 16);
    for (int i = t; i < 2112; i += THREADS)
        cp16(sb + SO_B2 + i * 16, (const char*)g_b2p + i * 16);
    if (t < 32) cp16(sb + SO_W3 + t * 16, w3g + t * 4);
    asm volatile("cp.async.commit_group;\n" ::: "memory");

    if (t == 0) sh_tile = atomicAdd(&g_ctr, 1u);
    asm volatile("cp.async.wait_group 0;\n" ::: "memory");
    __syncthreads();
    unsigned cur = sh_tile;

    float acc[4][8][4];             // mf x nf x quad

    while (cur < (unsigned)NT) {
        // ---- encoding: 128 px x 12 levels (12 tasks/thread) ----
        #pragma unroll
        for (int lv = 0; lv < 12; lv++)
            enc_one(tab, (char*)sm, (int)cur * PIX + t, lv, t);
        __syncthreads();

        // ====== GEMM1: K=48, warp tile 64x64 ======
        #pragma unroll
        for (int i = 0; i < 4; i++)
            #pragma unroll
            for (int j = 0; j < 8; j++)
                #pragma unroll
                for (int q = 0; q < 4; q++) acc[i][j][q] = 0.0f;

        {
            #pragma unroll
            for (int s = 0; s < 3; s++) {
                uint4 A[4];
                #pragma unroll
                for (int mf = 0; mf < 4; mf++)
                    A[mf] = *(const uint4*)(sm + A1FOFF(s, qc, (wm * 4 + mf) * 8 + qr));
                uint2 B[8];
                #pragma unroll
                for (int nf = 0; nf < 8; nf++)
                    B[nf] = *(const uint2*)(sm + B1OFF(s, qc, wn * 64 + nf * 8 + qr));
                #pragma unroll
                for (int mf = 0; mf < 4; mf++)
                    #pragma unroll
                    for (int nf = 0; nf < 8; nf++)
                        mmah(acc[mf][nf], A[mf].x, A[mf].y, A[mf].z, A[mf].w,
                             B[nf].x, B[nf].y);
            }
        }

        // ---- epilogue1: relu -> fp16 -> fragment-major uint4 A2 ----
        // warp owns cols wn*64..+63 -> ksteps s = wn*4 + j (j 0..3),
        // nf pair (2j, 2j+1); rows -> rg = wm*32 + mf*8 + qr.
        {
            #pragma unroll
            for (int mf = 0; mf < 4; mf++) {
                const int rg = wm * 32 + mf * 8 + qr;
                #pragma unroll
                for (int j = 0; j < 4; j++) {
                    const int nfA = 2 * j, nfB = 2 * j + 1;
                    uint4 v;
                    v.x = pk(fmaxf(acc[mf][nfA][0], 0.0f),
                             fmaxf(acc[mf][nfA][1], 0.0f));
                    v.y = pk(fmaxf(acc[mf][nfA][2], 0.0f),
                             fmaxf(acc[mf][nfA][3], 0.0f));
                    v.z = pk(fmaxf(acc[mf][nfB][0], 0.0f),
                             fmaxf(acc[mf][nfB][1], 0.0f));
                    v.w = pk(fmaxf(acc[mf][nfB][2], 0.0f),
                             fmaxf(acc[mf][nfB][3], 0.0f));
                    *(uint4*)(sm + A2FOFF(wn * 4 + j, qc, rg)) = v;
                }
            }
        }
        if (t == 0) sh_tile = atomicAdd(&g_ctr, 1u);
        __syncthreads();

        // ====== GEMM2: K=128, warp tile 64x64 ======
        #pragma unroll
        for (int i = 0; i < 4; i++)
            #pragma unroll
            for (int j = 0; j < 8; j++)
                #pragma unroll
                for (int q = 0; q < 4; q++) acc[i][j][q] = 0.0f;

        {
            #pragma unroll
            for (int s = 0; s < 8; s++) {
                uint4 A[4];
                #pragma unroll
                for (int mf = 0; mf < 4; mf++)
                    A[mf] = *(const uint4*)(sm + A2FOFF(s, qc, (wm * 4 + mf) * 8 + qr));
                uint2 B[8];
                #pragma unroll
                for (int nf = 0; nf < 8; nf++)
                    B[nf] = *(const uint2*)(sm + B2OFF(s, qc, wn * 64 + nf * 8 + qr));
                #pragma unroll
                for (int mf = 0; mf < 4; mf++)
                    #pragma unroll
                    for (int nf = 0; nf < 8; nf++)
                        mmah(acc[mf][nf], A[mf].x, A[mf].y, A[mf].z, A[mf].w,
                             B[nf].x, B[nf].y);
            }
        }

        // ---- epilogue2: dot w3, quad-reduce -> PARTS (2 partials/pixel) ----
        {
            const float* w3s = (const float*)(sm + SO_W3);
            float* parts = (float*)(sm + SO_PARTS);
            const int colb = wn * 64 + qc * 2;
            #pragma unroll
            for (int mf = 0; mf < 4; mf++) {
                float p0 = 0.0f, p1 = 0.0f;
                #pragma unroll
                for (int nf = 0; nf < 8; nf++) {
                    const int col = colb + nf * 8;
                    float wa = w3s[col], wb = w3s[col + 1];
                    p0 += fmaxf(acc[mf][nf][0], 0.0f) * wa
                        + fmaxf(acc[mf][nf][1], 0.0f) * wb;
                    p1 += fmaxf(acc[mf][nf][2], 0.0f) * wa
                        + fmaxf(acc[mf][nf][3], 0.0f) * wb;
                }
                p0 += __shfl_xor_sync(0xffffffffu, p0, 1);
                p0 += __shfl_xor_sync(0xffffffffu, p0, 2);
                p1 += __shfl_xor_sync(0xffffffffu, p1, 1);
                p1 += __shfl_xor_sync(0xffffffffu, p1, 2);
                if (qc == 0) {
                    const int r0 = wm * 64 + mf * 16 + qr;
                    parts[r0 * 2 + wn]       = p0;
                    parts[(r0 + 8) * 2 + wn] = p1;
                }
            }
        }
        __syncthreads();

        {
            const float* q = (const float*)(sm + SO_PARTS) + t * 2;
            out[cur * PIX + t] = (q[0] + q[1]) * OUT_SCALE;
        }

        const unsigned nxt = sh_tile;
        __syncthreads();     // PARTS read done; A1F free for next encoding
        cur = nxt;
    }
}

extern "C" void kernel_launch(void* const* d_in, const int* in_sizes, int n_in,
                              void* d_out, int out_size)
{
    // inputs: [0]=H, [1]=W, [2]=table f32[12*2^20*4],
    //         [3]=w1 f32[48*128], [4]=w2 f32[128*128], [5]=w3 f32[128]
    const float* tab = (const float*)d_in[2];
    const float* w1  = (const float*)d_in[3];
    const float* w2  = (const float*)d_in[4];
    const float* w3  = (const float*)d_in[5];
    float* out = (float*)d_out;

    cudaFuncSetAttribute(inr_mma_kernel,
                         cudaFuncAttributeMaxDynamicSharedMemorySize, SMEM_BYTES);

    prep_kernel<<<17, 256>>>(w1, w2);      // packs weights, resets g_ctr
    const int NT = out_size / PIX;         // 8192 tiles
    inr_mma_kernel<<<304, THREADS, SMEM_BYTES>>>(tab, w3, out, NT);
}